// round 2
// baseline (speedup 1.0000x reference)
#include <cuda_runtime.h>

#define EMB 1024
#define NH 16
#define HD 64
#define SEQ 8192
#define GL 128
#define BLK 512
#define NB 16          // num local blocks
#define LTOT 8320      // GL + SEQ (concat rows: global first)
#define KSPLIT 16      // key splits for global attention
#define KPS 520        // keys per split (8320/16)
#define GCH 40         // global-attn key chunk (520 = 13*40)
#define LCH 64         // local-attn key chunk (640 = 10*64)

// -------- scratch (static device allocations; no cudaMalloc) --------
__device__ float g_X[(size_t)LTOT * EMB];
__device__ float g_Q[(size_t)LTOT * EMB];
__device__ float g_K[(size_t)LTOT * EMB];
__device__ float g_V[(size_t)LTOT * EMB];
__device__ float g_Og[(size_t)GL * EMB];     // global-attn out (pre-Wo)
__device__ float g_Ol[(size_t)SEQ * EMB];    // local-attn out (pre-Wo)
__device__ float g_part[(size_t)NH * KSPLIT * GL * (HD + 2)];  // m, l, acc[64]

// -------- concat [global; token] into g_X --------
__global__ void concat_kernel(const float* __restrict__ glob,
                              const float* __restrict__ tok) {
    size_t i = (size_t)blockIdx.x * blockDim.x + threadIdx.x;
    size_t total = (size_t)LTOT * EMB;
    if (i < total) {
        g_X[i] = (i < (size_t)GL * EMB) ? glob[i] : tok[i - (size_t)GL * EMB];
    }
}

// -------- classic tiled fp32 GEMM: C[M,1024] = A[M,1024] @ B[1024,1024] * scale
// BM=BN=128, BK=8, 256 threads, 8x8 per thread. M % 128 == 0 assumed.
__global__ __launch_bounds__(256) void gemm128(const float* __restrict__ A,
                                               const float* __restrict__ B,
                                               float* __restrict__ C,
                                               float scale) {
    __shared__ float As[8][128];
    __shared__ float Bs[8][128];
    int bm = blockIdx.y, bn = blockIdx.x;
    int t = threadIdx.x;
    int tx = t & 15, ty = t >> 4;

    const float* Ablk = A + (size_t)bm * 128 * EMB;
    const float* Bblk = B + (size_t)bn * 128;

    int arow = t >> 1, acol = (t & 1) * 4;
    int brow = t >> 5, bcol = (t & 31) * 4;

    float acc[8][8];
#pragma unroll
    for (int i = 0; i < 8; i++)
#pragma unroll
        for (int j = 0; j < 8; j++) acc[i][j] = 0.f;

    for (int k0 = 0; k0 < EMB; k0 += 8) {
        float4 av = *(const float4*)(Ablk + (size_t)arow * EMB + k0 + acol);
        As[acol + 0][arow] = av.x;
        As[acol + 1][arow] = av.y;
        As[acol + 2][arow] = av.z;
        As[acol + 3][arow] = av.w;
        float4 bv = *(const float4*)(Bblk + (size_t)(k0 + brow) * EMB + bcol);
        *(float4*)&Bs[brow][bcol] = bv;
        __syncthreads();
#pragma unroll
        for (int k = 0; k < 8; k++) {
            float a[8], b[8];
            *(float4*)(a + 0) = *(float4*)&As[k][ty * 8 + 0];
            *(float4*)(a + 4) = *(float4*)&As[k][ty * 8 + 4];
            *(float4*)(b + 0) = *(float4*)&Bs[k][tx * 8 + 0];
            *(float4*)(b + 4) = *(float4*)&Bs[k][tx * 8 + 4];
#pragma unroll
            for (int i = 0; i < 8; i++)
#pragma unroll
                for (int j = 0; j < 8; j++) acc[i][j] += a[i] * b[j];
        }
        __syncthreads();
    }

    float* Cb = C + (size_t)(bm * 128 + ty * 8) * EMB + bn * 128 + tx * 8;
#pragma unroll
    for (int i = 0; i < 8; i++) {
        float4 v0, v1;
        v0.x = acc[i][0] * scale; v0.y = acc[i][1] * scale;
        v0.z = acc[i][2] * scale; v0.w = acc[i][3] * scale;
        v1.x = acc[i][4] * scale; v1.y = acc[i][5] * scale;
        v1.z = acc[i][6] * scale; v1.w = acc[i][7] * scale;
        *(float4*)(Cb + (size_t)i * EMB + 0) = v0;
        *(float4*)(Cb + (size_t)i * EMB + 4) = v1;
    }
}

// -------- global attention, split-K partials --------
// grid (KSPLIT, NH), block 128: thread = global q row. Online softmax over
// this split's 520 keys; store (m, l, acc[64]) partial.
__global__ __launch_bounds__(128) void gattn_partial(const float* __restrict__ mask) {
    int ks = blockIdx.x, h = blockIdx.y;
    int qi = threadIdx.x;
    __shared__ float Ks[GCH][HD];
    __shared__ float Vs[GCH][HD];

    float q[HD];
    const float* qp = g_Q + (size_t)qi * EMB + h * HD;
#pragma unroll
    for (int d = 0; d < HD; d += 4) *(float4*)(q + d) = *(const float4*)(qp + d);

    float m = -1e30f, l = 0.f;
    float acc[HD];
#pragma unroll
    for (int d = 0; d < HD; d++) acc[d] = 0.f;

    int kbase = ks * KPS;
    for (int c0 = 0; c0 < KPS; c0 += GCH) {
        __syncthreads();
        for (int i = threadIdx.x; i < GCH * (HD / 4); i += 128) {
            int r = i / (HD / 4), cc = (i % (HD / 4)) * 4;
            size_t off = (size_t)(kbase + c0 + r) * EMB + h * HD + cc;
            *(float4*)&Ks[r][cc] = *(const float4*)(g_K + off);
            *(float4*)&Vs[r][cc] = *(const float4*)(g_V + off);
        }
        __syncthreads();
        for (int c = 0; c < GCH; c++) {
            int x = kbase + c0 + c;
            float s = (x >= GL) ? mask[x - GL] : 0.f;
#pragma unroll
            for (int d = 0; d < HD; d += 4) {
                float4 kv = *(float4*)&Ks[c][d];
                s += q[d] * kv.x + q[d + 1] * kv.y + q[d + 2] * kv.z + q[d + 3] * kv.w;
            }
            if (s > m) {
                float corr = __expf(m - s);
                l *= corr;
#pragma unroll
                for (int d = 0; d < HD; d++) acc[d] *= corr;
                m = s;
            }
            float p = __expf(s - m);
            l += p;
#pragma unroll
            for (int d = 0; d < HD; d += 4) {
                float4 vv = *(float4*)&Vs[c][d];
                acc[d] += p * vv.x;
                acc[d + 1] += p * vv.y;
                acc[d + 2] += p * vv.z;
                acc[d + 3] += p * vv.w;
            }
        }
    }

    float* pp = g_part + (((size_t)h * KSPLIT + ks) * GL + qi) * (HD + 2);
    pp[0] = m;
    pp[1] = l;
#pragma unroll
    for (int d = 0; d < HD; d++) pp[2 + d] = acc[d];
}

// -------- combine global-attn partials --------
__global__ __launch_bounds__(128) void gattn_combine() {
    int h = blockIdx.x;
    int qi = threadIdx.x;
    float M = -1e30f;
    for (int ks = 0; ks < KSPLIT; ks++) {
        const float* pp = g_part + (((size_t)h * KSPLIT + ks) * GL + qi) * (HD + 2);
        M = fmaxf(M, pp[0]);
    }
    float L = 0.f;
    float out[HD];
#pragma unroll
    for (int d = 0; d < HD; d++) out[d] = 0.f;
    for (int ks = 0; ks < KSPLIT; ks++) {
        const float* pp = g_part + (((size_t)h * KSPLIT + ks) * GL + qi) * (HD + 2);
        float w = __expf(pp[0] - M);
        L += pp[1] * w;
#pragma unroll
        for (int d = 0; d < HD; d++) out[d] += pp[2 + d] * w;
    }
    float inv = 1.f / L;
    float* op = g_Og + (size_t)qi * EMB + h * HD;
#pragma unroll
    for (int d = 0; d < HD; d++) op[d] = out[d] * inv;
}

// -------- local attention --------
// grid (4 qtiles, NB, NH), block 128: thread = q row within tile.
// keys = [128 global] + [512 block-local] = 640 = 10 chunks of 64.
__global__ __launch_bounds__(128) void lattn(const float* __restrict__ mask) {
    int qt = blockIdx.x, n = blockIdx.y, h = blockIdx.z;
    int ti = threadIdx.x;
    __shared__ float Ks[LCH][HD];
    __shared__ float Vs[LCH][HD];

    int tokrow = n * BLK + qt * 128 + ti;      // 0..8191
    int qrow = GL + tokrow;                    // row in concat layout

    float q[HD];
    const float* qp = g_Q + (size_t)qrow * EMB + h * HD;
#pragma unroll
    for (int d = 0; d < HD; d += 4) *(float4*)(q + d) = *(const float4*)(qp + d);

    float m = -1e30f, l = 0.f;
    float acc[HD];
#pragma unroll
    for (int d = 0; d < HD; d++) acc[d] = 0.f;

    for (int c0 = 0; c0 < GL + BLK; c0 += LCH) {
        __syncthreads();
        for (int i = ti; i < LCH * (HD / 4); i += 128) {
            int r = i / (HD / 4), cc = (i % (HD / 4)) * 4;
            int x = c0 + r;
            int krow = (x < GL) ? x : (GL + n * BLK + (x - GL));
            size_t off = (size_t)krow * EMB + h * HD + cc;
            *(float4*)&Ks[r][cc] = *(const float4*)(g_K + off);
            *(float4*)&Vs[r][cc] = *(const float4*)(g_V + off);
        }
        __syncthreads();
        for (int c = 0; c < LCH; c++) {
            int x = c0 + c;
            float s = (x >= GL) ? mask[n * BLK + x - GL] : 0.f;
#pragma unroll
            for (int d = 0; d < HD; d += 4) {
                float4 kv = *(float4*)&Ks[c][d];
                s += q[d] * kv.x + q[d + 1] * kv.y + q[d + 2] * kv.z + q[d + 3] * kv.w;
            }
            if (s > m) {
                float corr = __expf(m - s);
                l *= corr;
#pragma unroll
                for (int d = 0; d < HD; d++) acc[d] *= corr;
                m = s;
            }
            float p = __expf(s - m);
            l += p;
#pragma unroll
            for (int d = 0; d < HD; d += 4) {
                float4 vv = *(float4*)&Vs[c][d];
                acc[d] += p * vv.x;
                acc[d + 1] += p * vv.y;
                acc[d + 2] += p * vv.z;
                acc[d + 3] += p * vv.w;
            }
        }
    }

    float inv = 1.f / l;
    float* op = g_Ol + (size_t)tokrow * EMB + h * HD;
#pragma unroll
    for (int d = 0; d < HD; d++) op[d] = acc[d] * inv;
}

extern "C" void kernel_launch(void* const* d_in, const int* in_sizes, int n_in,
                              void* d_out, int out_size) {
    const float* tok = (const float*)d_in[0];   // [1,8192,1024]
    const float* glob = (const float*)d_in[1];  // [1,128,1024]
    const float* mask = (const float*)d_in[2];  // [1,8192]
    const float* Wq = (const float*)d_in[3];
    const float* Wk = (const float*)d_in[4];
    const float* Wv = (const float*)d_in[5];
    const float* Wo = (const float*)d_in[6];
    float* out = (float*)d_out;  // [l_out (8192*1024); g_out (128*1024)]

    float *pX, *pQ, *pK, *pV, *pOg, *pOl;
    cudaGetSymbolAddress((void**)&pX, g_X);
    cudaGetSymbolAddress((void**)&pQ, g_Q);
    cudaGetSymbolAddress((void**)&pK, g_K);
    cudaGetSymbolAddress((void**)&pV, g_V);
    cudaGetSymbolAddress((void**)&pOg, g_Og);
    cudaGetSymbolAddress((void**)&pOl, g_Ol);

    const float scaling = 0.125f;  // D^-0.5 = 64^-0.5

    // 1. concat [global; token]
    {
        size_t total = (size_t)LTOT * EMB;
        int threads = 256;
        int blocks = (int)((total + threads - 1) / threads);
        concat_kernel<<<blocks, threads>>>(glob, tok);
    }

    // 2. projections
    gemm128<<<dim3(8, LTOT / 128), 256>>>(pX, Wq, pQ, scaling);
    gemm128<<<dim3(8, LTOT / 128), 256>>>(pX, Wk, pK, 1.f);
    gemm128<<<dim3(8, LTOT / 128), 256>>>(pX, Wv, pV, 1.f);

    // 3. global attention (split-K + combine)
    gattn_partial<<<dim3(KSPLIT, NH), 128>>>(mask);
    gattn_combine<<<NH, 128>>>();

    // 4. local attention
    lattn<<<dim3(4, NB, NH), 128>>>(mask);

    // 5. output projections
    gemm128<<<dim3(8, SEQ / 128), 256>>>(pOl, Wo, out, 1.f);
    gemm128<<<dim3(8, GL / 128), 256>>>(pOg, Wo, out + (size_t)SEQ * EMB, 1.f);
}

// round 3
// speedup vs baseline: 1.0536x; 1.0536x over previous
#include <cuda_runtime.h>

#define EMB 1024
#define NH 16
#define HD 64
#define SEQ 8192
#define GL 128
#define BLK 512
#define NB 16
#define LTOT 8320
#define KSPLIT 16
#define KPS 520
#define GCH 40
#define LCH 64

typedef unsigned long long u64;

// ---------- packed fp32x2 helpers (Blackwell FFMA2: exact rn per lane) ----------
__device__ __forceinline__ u64 dup2(float v) {
    u64 r; asm("mov.b64 %0,{%1,%1};" : "=l"(r) : "f"(v)); return r;
}
__device__ __forceinline__ float2 up2(u64 v) {
    float2 f; asm("mov.b64 {%0,%1},%2;" : "=f"(f.x), "=f"(f.y) : "l"(v)); return f;
}
__device__ __forceinline__ u64 ffma2(u64 a, u64 b, u64 c) {
    u64 d; asm("fma.rn.f32x2 %0,%1,%2,%3;" : "=l"(d) : "l"(a), "l"(b), "l"(c)); return d;
}
__device__ __forceinline__ u64 fmul2(u64 a, u64 b) {
    u64 d; asm("mul.rn.f32x2 %0,%1,%2;" : "=l"(d) : "l"(a), "l"(b)); return d;
}

// -------- scratch --------
__device__ float g_X[(size_t)LTOT * EMB];
__device__ float g_Q[(size_t)LTOT * EMB];
__device__ float g_K[(size_t)LTOT * EMB];
__device__ float g_V[(size_t)LTOT * EMB];
__device__ float g_Og[(size_t)GL * EMB];
__device__ float g_Ol[(size_t)SEQ * EMB];
__device__ float g_part[(size_t)NH * KSPLIT * GL * (HD + 2)];

// -------- concat [global; token] (vectorized) --------
__global__ void concat_kernel(const float4* __restrict__ glob,
                              const float4* __restrict__ tok) {
    size_t i = (size_t)blockIdx.x * blockDim.x + threadIdx.x;
    size_t gl4 = (size_t)GL * EMB / 4;
    size_t tot4 = (size_t)LTOT * EMB / 4;
    if (i < tot4) {
        ((float4*)g_X)[i] = (i < gl4) ? glob[i] : tok[i - gl4];
    }
}

// -------- tiled fp32 GEMM with FFMA2 inner loop --------
// C[M,1024] = A[M,1024] @ B[1024,1024] * scale. BM=BN=128, BK=8, 256 thr, 8x8/thread.
__global__ __launch_bounds__(256) void gemm128(const float* __restrict__ A,
                                               const float* __restrict__ B,
                                               float* __restrict__ C,
                                               float scale) {
    __shared__ float As[8][128];
    __shared__ float Bs[8][128];
    int bm = blockIdx.y, bn = blockIdx.x;
    int t = threadIdx.x;
    int tx = t & 15, ty = t >> 4;

    int arow = t >> 1, acol = (t & 1) * 4;
    int brow = t >> 5, bcol = (t & 31) * 4;

    const float* Aptr = A + (size_t)(bm * 128 + arow) * EMB + acol;
    const float* Bptr = B + (size_t)brow * EMB + bn * 128 + bcol;

    u64 acc[8][4];
#pragma unroll
    for (int i = 0; i < 8; i++)
#pragma unroll
        for (int j = 0; j < 4; j++) acc[i][j] = 0ull;

    // prefetch first tile
    float4 av = *(const float4*)(Aptr);
    float4 bv = *(const float4*)(Bptr);

    for (int k0 = 0; k0 < EMB; k0 += 8) {
        As[acol + 0][arow] = av.x;
        As[acol + 1][arow] = av.y;
        As[acol + 2][arow] = av.z;
        As[acol + 3][arow] = av.w;
        *(float4*)&Bs[brow][bcol] = bv;
        __syncthreads();
        if (k0 + 8 < EMB) {
            av = *(const float4*)(Aptr + k0 + 8);
            bv = *(const float4*)(Bptr + (size_t)(k0 + 8) * EMB);
        }
#pragma unroll
        for (int k = 0; k < 8; k++) {
            float4 a0 = *(const float4*)&As[k][ty * 8];
            float4 a1 = *(const float4*)&As[k][ty * 8 + 4];
            ulonglong2 b0 = *(const ulonglong2*)&Bs[k][tx * 8];
            ulonglong2 b1 = *(const ulonglong2*)&Bs[k][tx * 8 + 4];
            u64 ad;
#define GEMM_ROW(r, aval)                                   \
            ad = dup2(aval);                                 \
            acc[r][0] = ffma2(ad, b0.x, acc[r][0]);          \
            acc[r][1] = ffma2(ad, b0.y, acc[r][1]);          \
            acc[r][2] = ffma2(ad, b1.x, acc[r][2]);          \
            acc[r][3] = ffma2(ad, b1.y, acc[r][3]);
            GEMM_ROW(0, a0.x)
            GEMM_ROW(1, a0.y)
            GEMM_ROW(2, a0.z)
            GEMM_ROW(3, a0.w)
            GEMM_ROW(4, a1.x)
            GEMM_ROW(5, a1.y)
            GEMM_ROW(6, a1.z)
            GEMM_ROW(7, a1.w)
#undef GEMM_ROW
        }
        __syncthreads();
    }

    float* Cb = C + (size_t)(bm * 128 + ty * 8) * EMB + bn * 128 + tx * 8;
#pragma unroll
    for (int i = 0; i < 8; i++) {
        float2 p0 = up2(acc[i][0]), p1 = up2(acc[i][1]);
        float2 p2 = up2(acc[i][2]), p3 = up2(acc[i][3]);
        float4 v0, v1;
        v0.x = p0.x * scale; v0.y = p0.y * scale;
        v0.z = p1.x * scale; v0.w = p1.y * scale;
        v1.x = p2.x * scale; v1.y = p2.y * scale;
        v1.z = p3.x * scale; v1.w = p3.y * scale;
        *(float4*)(Cb + (size_t)i * EMB + 0) = v0;
        *(float4*)(Cb + (size_t)i * EMB + 4) = v1;
    }
}

// ---------- attention inner-step helpers ----------
// score: 4 independent f32x2 accumulators (breaks the latency chain)
__device__ __forceinline__ float dot64(const u64* __restrict__ q2,
                                       const float* __restrict__ krow) {
    u64 sa = 0ull, sb = 0ull, sc = 0ull, sd = 0ull;
#pragma unroll
    for (int dd = 0; dd < 4; dd++) {
        ulonglong2 k0v = *(const ulonglong2*)(krow + dd * 16);
        ulonglong2 k1v = *(const ulonglong2*)(krow + dd * 16 + 4);
        ulonglong2 k2v = *(const ulonglong2*)(krow + dd * 16 + 8);
        ulonglong2 k3v = *(const ulonglong2*)(krow + dd * 16 + 12);
        sa = ffma2(q2[dd * 8 + 0], k0v.x, sa);
        sb = ffma2(q2[dd * 8 + 1], k0v.y, sb);
        sc = ffma2(q2[dd * 8 + 2], k1v.x, sc);
        sd = ffma2(q2[dd * 8 + 3], k1v.y, sd);
        sa = ffma2(q2[dd * 8 + 4], k2v.x, sa);
        sb = ffma2(q2[dd * 8 + 5], k2v.y, sb);
        sc = ffma2(q2[dd * 8 + 6], k3v.x, sc);
        sd = ffma2(q2[dd * 8 + 7], k3v.y, sd);
    }
    float2 fa = up2(sa), fb = up2(sb), fc = up2(sc), fd = up2(sd);
    return ((fa.x + fa.y) + (fb.x + fb.y)) + ((fc.x + fc.y) + (fd.x + fd.y));
}

__device__ __forceinline__ void softmax_step(float s, float& m, float& l,
                                             u64* __restrict__ acc2,
                                             const float* __restrict__ vrow) {
    if (s > m) {
        float corr = __expf(m - s);
        l *= corr;
        u64 c2 = dup2(corr);
#pragma unroll
        for (int i = 0; i < 32; i++) acc2[i] = fmul2(acc2[i], c2);
        m = s;
    }
    float p = __expf(s - m);
    l += p;
    u64 p2 = dup2(p);
#pragma unroll
    for (int dd = 0; dd < 16; dd++) {
        ulonglong2 vv = *(const ulonglong2*)(vrow + dd * 4);
        acc2[2 * dd] = ffma2(p2, vv.x, acc2[2 * dd]);
        acc2[2 * dd + 1] = ffma2(p2, vv.y, acc2[2 * dd + 1]);
    }
}

// -------- global attention, split-K partials --------
__global__ __launch_bounds__(128) void gattn_partial(const float* __restrict__ mask) {
    int ks = blockIdx.x, h = blockIdx.y;
    int qi = threadIdx.x;
    __shared__ float Ks[GCH][HD];
    __shared__ float Vs[GCH][HD];
    __shared__ float Ms[GCH];

    u64 q2[32];
    const float* qp = g_Q + (size_t)qi * EMB + h * HD;
#pragma unroll
    for (int d2 = 0; d2 < 16; d2++) {
        ulonglong2 t2 = *(const ulonglong2*)(qp + d2 * 4);
        q2[2 * d2] = t2.x;
        q2[2 * d2 + 1] = t2.y;
    }

    float m = -1e30f, l = 0.f;
    u64 acc2[32];
#pragma unroll
    for (int i = 0; i < 32; i++) acc2[i] = 0ull;

    int kbase = ks * KPS;
    for (int c0 = 0; c0 < KPS; c0 += GCH) {
        __syncthreads();
        for (int i = threadIdx.x; i < GCH * (HD / 4); i += 128) {
            int r = i / (HD / 4), cc = (i % (HD / 4)) * 4;
            size_t off = (size_t)(kbase + c0 + r) * EMB + h * HD + cc;
            *(float4*)&Ks[r][cc] = *(const float4*)(g_K + off);
            *(float4*)&Vs[r][cc] = *(const float4*)(g_V + off);
        }
        if (threadIdx.x < GCH) {
            int x = kbase + c0 + threadIdx.x;
            Ms[threadIdx.x] = (x >= GL) ? mask[x - GL] : 0.f;
        }
        __syncthreads();
        for (int c = 0; c < GCH; c++) {
            float s = dot64(q2, &Ks[c][0]) + Ms[c];
            softmax_step(s, m, l, acc2, &Vs[c][0]);
        }
    }

    float* pp = g_part + (((size_t)h * KSPLIT + ks) * GL + qi) * (HD + 2);
    pp[0] = m;
    pp[1] = l;
#pragma unroll
    for (int dd = 0; dd < 16; dd++) {
        float2 x0 = up2(acc2[2 * dd]), x1 = up2(acc2[2 * dd + 1]);
        pp[2 + dd * 4 + 0] = x0.x;
        pp[2 + dd * 4 + 1] = x0.y;
        pp[2 + dd * 4 + 2] = x1.x;
        pp[2 + dd * 4 + 3] = x1.y;
    }
}

// -------- combine global-attn partials --------
__global__ __launch_bounds__(128) void gattn_combine() {
    int h = blockIdx.x;
    int qi = threadIdx.x;
    float M = -1e30f;
    for (int ks = 0; ks < KSPLIT; ks++) {
        const float* pp = g_part + (((size_t)h * KSPLIT + ks) * GL + qi) * (HD + 2);
        M = fmaxf(M, pp[0]);
    }
    float L = 0.f;
    float out[HD];
#pragma unroll
    for (int d = 0; d < HD; d++) out[d] = 0.f;
    for (int ks = 0; ks < KSPLIT; ks++) {
        const float* pp = g_part + (((size_t)h * KSPLIT + ks) * GL + qi) * (HD + 2);
        float w = __expf(pp[0] - M);
        L += pp[1] * w;
#pragma unroll
        for (int d = 0; d < HD; d++) out[d] += pp[2 + d] * w;
    }
    float inv = 1.f / L;
    float* op = g_Og + (size_t)qi * EMB + h * HD;
#pragma unroll
    for (int d = 0; d < HD; d++) op[d] = out[d] * inv;
}

// -------- local attention --------
__global__ __launch_bounds__(128) void lattn(const float* __restrict__ mask) {
    int qt = blockIdx.x, n = blockIdx.y, h = blockIdx.z;
    int ti = threadIdx.x;
    __shared__ float Ks[LCH][HD];
    __shared__ float Vs[LCH][HD];
    __shared__ float Ms[LCH];

    int tokrow = n * BLK + qt * 128 + ti;
    int qrow = GL + tokrow;

    u64 q2[32];
    const float* qp = g_Q + (size_t)qrow * EMB + h * HD;
#pragma unroll
    for (int d2 = 0; d2 < 16; d2++) {
        ulonglong2 t2 = *(const ulonglong2*)(qp + d2 * 4);
        q2[2 * d2] = t2.x;
        q2[2 * d2 + 1] = t2.y;
    }

    float m = -1e30f, l = 0.f;
    u64 acc2[32];
#pragma unroll
    for (int i = 0; i < 32; i++) acc2[i] = 0ull;

    for (int c0 = 0; c0 < GL + BLK; c0 += LCH) {
        __syncthreads();
        for (int i = ti; i < LCH * (HD / 4); i += 128) {
            int r = i / (HD / 4), cc = (i % (HD / 4)) * 4;
            int x = c0 + r;
            int krow = (x < GL) ? x : (GL + n * BLK + (x - GL));
            size_t off = (size_t)krow * EMB + h * HD + cc;
            *(float4*)&Ks[r][cc] = *(const float4*)(g_K + off);
            *(float4*)&Vs[r][cc] = *(const float4*)(g_V + off);
        }
        if (ti < LCH) {
            int x = c0 + ti;
            Ms[ti] = (x >= GL) ? mask[n * BLK + x - GL] : 0.f;
        }
        __syncthreads();
        for (int c = 0; c < LCH; c++) {
            float s = dot64(q2, &Ks[c][0]) + Ms[c];
            softmax_step(s, m, l, acc2, &Vs[c][0]);
        }
    }

    float inv = 1.f / l;
    float* op = g_Ol + (size_t)tokrow * EMB + h * HD;
#pragma unroll
    for (int dd = 0; dd < 16; dd++) {
        float2 x0 = up2(acc2[2 * dd]), x1 = up2(acc2[2 * dd + 1]);
        float4 o;
        o.x = x0.x * inv; o.y = x0.y * inv;
        o.z = x1.x * inv; o.w = x1.y * inv;
        *(float4*)(op + dd * 4) = o;
    }
}

extern "C" void kernel_launch(void* const* d_in, const int* in_sizes, int n_in,
                              void* d_out, int out_size) {
    const float* tok = (const float*)d_in[0];
    const float* glob = (const float*)d_in[1];
    const float* mask = (const float*)d_in[2];
    const float* Wq = (const float*)d_in[3];
    const float* Wk = (const float*)d_in[4];
    const float* Wv = (const float*)d_in[5];
    const float* Wo = (const float*)d_in[6];
    float* out = (float*)d_out;

    float *pX, *pQ, *pK, *pV, *pOg, *pOl;
    cudaGetSymbolAddress((void**)&pX, g_X);
    cudaGetSymbolAddress((void**)&pQ, g_Q);
    cudaGetSymbolAddress((void**)&pK, g_K);
    cudaGetSymbolAddress((void**)&pV, g_V);
    cudaGetSymbolAddress((void**)&pOg, g_Og);
    cudaGetSymbolAddress((void**)&pOl, g_Ol);

    const float scaling = 0.125f;

    {
        size_t tot4 = (size_t)LTOT * EMB / 4;
        int threads = 256;
        int blocks = (int)((tot4 + threads - 1) / threads);
        concat_kernel<<<blocks, threads>>>((const float4*)glob, (const float4*)tok);
    }

    gemm128<<<dim3(8, LTOT / 128), 256>>>(pX, Wq, pQ, scaling);
    gemm128<<<dim3(8, LTOT / 128), 256>>>(pX, Wk, pK, 1.f);
    gemm128<<<dim3(8, LTOT / 128), 256>>>(pX, Wv, pV, 1.f);

    gattn_partial<<<dim3(KSPLIT, NH), 128>>>(mask);
    gattn_combine<<<NH, 128>>>();

    lattn<<<dim3(4, NB, NH), 128>>>(mask);

    gemm128<<<dim3(8, SEQ / 128), 256>>>(pOl, Wo, out, 1.f);
    gemm128<<<dim3(8, GL / 128), 256>>>(pOg, Wo, out + (size_t)SEQ * EMB, 1.f);
}

// round 9
// speedup vs baseline: 1.1130x; 1.0564x over previous
#include <cuda_runtime.h>
#include <cuda_bf16.h>
#include <cstdint>

#define EMB 1024
#define NH 16
#define HD 64
#define SEQ 8192
#define GL 128
#define BLK 512
#define NB 16
#define LTOT 8320
#define KSPLIT 16
#define KPS 520
#define GCH 40
#define LCH 64

typedef unsigned long long u64;

// ================= packed fp32x2 helpers (attention kernels) =================
__device__ __forceinline__ u64 dup2(float v) {
    u64 r; asm("mov.b64 %0,{%1,%1};" : "=l"(r) : "f"(v)); return r;
}
__device__ __forceinline__ float2 up2(u64 v) {
    float2 f; asm("mov.b64 {%0,%1},%2;" : "=f"(f.x), "=f"(f.y) : "l"(v)); return f;
}
__device__ __forceinline__ u64 ffma2(u64 a, u64 b, u64 c) {
    u64 d; asm("fma.rn.f32x2 %0,%1,%2,%3;" : "=l"(d) : "l"(a), "l"(b), "l"(c)); return d;
}
__device__ __forceinline__ u64 fmul2(u64 a, u64 b) {
    u64 d; asm("mul.rn.f32x2 %0,%1,%2;" : "=l"(d) : "l"(a), "l"(b)); return d;
}

// ================= scratch =================
__device__ __nv_bfloat16 g_Xhi[(size_t)LTOT * EMB];
__device__ __nv_bfloat16 g_Xlo[(size_t)LTOT * EMB];
__device__ __nv_bfloat16 g_Whi[(size_t)4 * EMB * EMB];  // transposed [N,K], 4 weights
__device__ __nv_bfloat16 g_Wlo[(size_t)4 * EMB * EMB];
__device__ float g_Q[(size_t)LTOT * EMB];
__device__ float g_K[(size_t)LTOT * EMB];
__device__ float g_V[(size_t)LTOT * EMB];
__device__ float g_O[(size_t)LTOT * EMB];   // rows 0..8191 local out, 8192.. global out
__device__ float g_part[(size_t)NH * KSPLIT * GL * (HD + 2)];

// ================= PTX helpers (arch-neutral: sm_80+) =================
__device__ __forceinline__ uint32_t smem_u32(const void* p) {
    uint32_t a;
    asm("{ .reg .u64 t; cvta.to.shared.u64 t, %1; cvt.u32.u64 %0, t; }" : "=r"(a) : "l"(p));
    return a;
}
__device__ __forceinline__ void cp16(uint32_t s, const void* g) {
    asm volatile("cp.async.cg.shared.global [%0], [%1], 16;" :: "r"(s), "l"(g));
}

#define LDSM_X4(r, addr)                                                          \
    asm volatile("ldmatrix.sync.aligned.m8n8.x4.shared.b16 {%0,%1,%2,%3},[%4];"   \
        : "=r"((r)[0]), "=r"((r)[1]), "=r"((r)[2]), "=r"((r)[3]) : "r"(addr))

#define MMA_BF16(c, a, b)                                                          \
    asm volatile("mma.sync.aligned.m16n8k16.row.col.f32.bf16.bf16.f32 "            \
        "{%0,%1,%2,%3},{%4,%5,%6,%7},{%8,%9},{%0,%1,%2,%3};"                       \
        : "+f"((c)[0]), "+f"((c)[1]), "+f"((c)[2]), "+f"((c)[3])                   \
        : "r"((a)[0]), "r"((a)[1]), "r"((a)[2]), "r"((a)[3]),                      \
          "r"((b)[0]), "r"((b)[1]))

// ================= conversion kernels =================
__global__ void cvt_x(const float4* __restrict__ glob, const float4* __restrict__ tok) {
    size_t i = (size_t)blockIdx.x * blockDim.x + threadIdx.x;
    size_t gl4 = (size_t)GL * EMB / 4, tot4 = (size_t)LTOT * EMB / 4;
    if (i >= tot4) return;
    float4 v = (i < gl4) ? glob[i] : tok[i - gl4];
    __nv_bfloat16 h[4], lo[4];
    float f[4] = {v.x, v.y, v.z, v.w};
#pragma unroll
    for (int j = 0; j < 4; j++) {
        h[j] = __float2bfloat16_rn(f[j]);
        lo[j] = __float2bfloat16_rn(f[j] - __bfloat162float(h[j]));
    }
    *(ushort4*)&g_Xhi[i * 4] = *(ushort4*)h;
    *(ushort4*)&g_Xlo[i * 4] = *(ushort4*)lo;
}

__global__ void cvt_o() {
    size_t i = (size_t)blockIdx.x * blockDim.x + threadIdx.x;
    size_t tot4 = (size_t)LTOT * EMB / 4;
    if (i >= tot4) return;
    float4 v = ((const float4*)g_O)[i];
    __nv_bfloat16 h[4], lo[4];
    float f[4] = {v.x, v.y, v.z, v.w};
#pragma unroll
    for (int j = 0; j < 4; j++) {
        h[j] = __float2bfloat16_rn(f[j]);
        lo[j] = __float2bfloat16_rn(f[j] - __bfloat162float(h[j]));
    }
    *(ushort4*)&g_Xhi[i * 4] = *(ushort4*)h;
    *(ushort4*)&g_Xlo[i * 4] = *(ushort4*)lo;
}

// transpose + split weights: W[k][n] fp32 -> Wt_hi/lo[n][k] bf16
__global__ void cvt_w(const float* __restrict__ W0, const float* __restrict__ W1,
                      const float* __restrict__ W2, const float* __restrict__ W3) {
    __shared__ float s[32][33];
    int w = blockIdx.z;
    const float* W = (w == 0) ? W0 : (w == 1) ? W1 : (w == 2) ? W2 : W3;
    __nv_bfloat16* hi = g_Whi + ((size_t)w << 20);
    __nv_bfloat16* lo = g_Wlo + ((size_t)w << 20);
    int k0 = blockIdx.x * 32, n0 = blockIdx.y * 32;
    int tx = threadIdx.x, ty = threadIdx.y;  // 32 x 8
#pragma unroll
    for (int i = 0; i < 4; i++)
        s[ty + i * 8][tx] = W[(size_t)(k0 + ty + i * 8) * EMB + n0 + tx];
    __syncthreads();
#pragma unroll
    for (int i = 0; i < 4; i++) {
        float v = s[tx][ty + i * 8];
        __nv_bfloat16 h = __float2bfloat16_rn(v);
        size_t off = (size_t)(n0 + ty + i * 8) * EMB + k0 + tx;
        hi[off] = h;
        lo[off] = __float2bfloat16_rn(v - __bfloat162float(h));
    }
}

// ================= bf16 split-GEMM on mma.sync (HMMA) =================
// C[M,1024] = (Ahi+Alo) @ (Whi+Wlo)^T * scale, B stored [N,K] K-major.
// 3 K-phases: Ahi*Bhi, Alo*Bhi, Ahi*Blo. CTA tile 128x128, BK=32, 2-stage cp.async.
// smem layout per stage: row-major 128 rows x 64B, 16B chunk XOR-swizzle:
//   off(row, chunk) = row*64 + ((chunk ^ ((row>>1)&3))<<4)
__global__ __launch_bounds__(256, 2) void gemm_mma(
    const __nv_bfloat16* __restrict__ Ahi, const __nv_bfloat16* __restrict__ Alo,
    const __nv_bfloat16* __restrict__ Bhi, const __nv_bfloat16* __restrict__ Blo,
    float* __restrict__ C, float scale) {
    __shared__ __align__(128) __nv_bfloat16 As[2][128 * 32];
    __shared__ __align__(128) __nv_bfloat16 Bs[2][128 * 32];

    int t = threadIdx.x, lane = t & 31, wid = t >> 5;
    int wm = wid >> 1, wn = wid & 1;          // warp grid 4 x 2
    int m0 = blockIdx.y * 128, n0 = blockIdx.x * 128;

    uint32_t sA = smem_u32(As), sB = smem_u32(Bs);

    // ldmatrix lane-address components
    // A frags: lanes0-7 rows+0 k0 | 8-15 rows+8 k0 | 16-23 rows+0 k8 | 24-31 rows+8 k8
    int khalfA = (lane >> 4) & 1;
    int rA = (lane & 7) + ((lane >> 3) & 1) * 8;
    int baseA[2], swA[2];
#pragma unroll
    for (int mt = 0; mt < 2; mt++) {
        int row = wm * 32 + mt * 16 + rA;
        baseA[mt] = row * 64;
        swA[mt] = (row >> 1) & 3;
    }
    // B frags: lanes0-7 ntile(2j) k0 | 8-15 ntile(2j) k8 | 16-23 ntile(2j+1) k0 | 24-31 k8
    int khalfB = (lane >> 3) & 1;
    int baseB[4], swB[4];
#pragma unroll
    for (int j = 0; j < 4; j++) {
        int row = wn * 64 + (2 * j + ((lane >> 4) & 1)) * 8 + (lane & 7);
        baseB[j] = row * 64;
        swB[j] = (row >> 1) & 3;
    }

    // cp.async write mapping (lane-invariant formula, 2 chunks per thread per tile)
    int ldr[2], ldso[2];
#pragma unroll
    for (int i = 0; i < 2; i++) {
        int idx = t + i * 256;
        int r = idx >> 2, ch = idx & 3;
        ldr[i] = r;
        ldso[i] = r * 64 + ((ch ^ ((r >> 1) & 3)) << 4);
    }
    int ldch[2] = {(t & 3) * 8, ((t + 256) & 3) * 8};

    float c[2][8][4];
#pragma unroll
    for (int mt = 0; mt < 2; mt++)
#pragma unroll
        for (int nt = 0; nt < 8; nt++)
#pragma unroll
            for (int k = 0; k < 4; k++) c[mt][nt][k] = 0.f;

#define LOAD_STAGE(kt, buf)                                                        \
    do {                                                                           \
        int p_ = (kt) >> 5;                                                        \
        int ksub_ = ((kt) & 31) * 32;                                              \
        const __nv_bfloat16* As_ = (p_ == 1) ? Alo : Ahi;                          \
        const __nv_bfloat16* Bs_ = (p_ == 2) ? Blo : Bhi;                          \
        _Pragma("unroll")                                                          \
        for (int i = 0; i < 2; i++) {                                              \
            cp16(sA + (buf) * 8192 + ldso[i],                                      \
                 As_ + (size_t)(m0 + ldr[i]) * EMB + ksub_ + ldch[i]);             \
            cp16(sB + (buf) * 8192 + ldso[i],                                      \
                 Bs_ + (size_t)(n0 + ldr[i]) * EMB + ksub_ + ldch[i]);             \
        }                                                                          \
        asm volatile("cp.async.commit_group;" ::: "memory");                       \
    } while (0)

    LOAD_STAGE(0, 0);

    for (int kt = 0; kt < 96; kt++) {
        int buf = kt & 1;
        if (kt + 1 < 96) {
            LOAD_STAGE(kt + 1, (kt + 1) & 1);
            asm volatile("cp.async.wait_group 1;" ::: "memory");
        } else {
            asm volatile("cp.async.wait_group 0;" ::: "memory");
        }
        __syncthreads();

#pragma unroll
        for (int ks = 0; ks < 2; ks++) {
            uint32_t af[2][4], bf[8][2];
#pragma unroll
            for (int mt = 0; mt < 2; mt++) {
                uint32_t addr = sA + buf * 8192 + baseA[mt] +
                                (((ks * 2 + khalfA) ^ swA[mt]) << 4);
                LDSM_X4(af[mt], addr);
            }
#pragma unroll
            for (int j = 0; j < 4; j++) {
                uint32_t r[4];
                uint32_t addr = sB + buf * 8192 + baseB[j] +
                                (((ks * 2 + khalfB) ^ swB[j]) << 4);
                LDSM_X4(r, addr);
                bf[2 * j][0] = r[0]; bf[2 * j][1] = r[1];
                bf[2 * j + 1][0] = r[2]; bf[2 * j + 1][1] = r[3];
            }
#pragma unroll
            for (int mt = 0; mt < 2; mt++)
#pragma unroll
                for (int nt = 0; nt < 8; nt++)
                    MMA_BF16(c[mt][nt], af[mt], bf[nt]);
        }
        __syncthreads();
    }
#undef LOAD_STAGE

    // epilogue: direct fragment stores
    int g = lane >> 2, tig = lane & 3;
#pragma unroll
    for (int mt = 0; mt < 2; mt++) {
#pragma unroll
        for (int nt = 0; nt < 8; nt++) {
            int row = m0 + wm * 32 + mt * 16 + g;
            int col = n0 + wn * 64 + nt * 8 + tig * 2;
            float2 v0 = {c[mt][nt][0] * scale, c[mt][nt][1] * scale};
            float2 v1 = {c[mt][nt][2] * scale, c[mt][nt][3] * scale};
            *(float2*)(C + (size_t)row * EMB + col) = v0;
            *(float2*)(C + (size_t)(row + 8) * EMB + col) = v1;
        }
    }
}

// ================= attention =================
__device__ __forceinline__ float dot64(const u64* __restrict__ q2,
                                       const float* __restrict__ krow) {
    u64 sa = 0ull, sb = 0ull, sc = 0ull, sd = 0ull;
#pragma unroll
    for (int dd = 0; dd < 4; dd++) {
        ulonglong2 k0v = *(const ulonglong2*)(krow + dd * 16);
        ulonglong2 k1v = *(const ulonglong2*)(krow + dd * 16 + 4);
        ulonglong2 k2v = *(const ulonglong2*)(krow + dd * 16 + 8);
        ulonglong2 k3v = *(const ulonglong2*)(krow + dd * 16 + 12);
        sa = ffma2(q2[dd * 8 + 0], k0v.x, sa);
        sb = ffma2(q2[dd * 8 + 1], k0v.y, sb);
        sc = ffma2(q2[dd * 8 + 2], k1v.x, sc);
        sd = ffma2(q2[dd * 8 + 3], k1v.y, sd);
        sa = ffma2(q2[dd * 8 + 4], k2v.x, sa);
        sb = ffma2(q2[dd * 8 + 5], k2v.y, sb);
        sc = ffma2(q2[dd * 8 + 6], k3v.x, sc);
        sd = ffma2(q2[dd * 8 + 7], k3v.y, sd);
    }
    float2 fa = up2(sa), fb = up2(sb), fc = up2(sc), fd = up2(sd);
    return ((fa.x + fa.y) + (fb.x + fb.y)) + ((fc.x + fc.y) + (fd.x + fd.y));
}

__device__ __forceinline__ void softmax_step(float s, float& m, float& l,
                                             u64* __restrict__ acc2,
                                             const float* __restrict__ vrow) {
    if (s > m) {
        float corr = __expf(m - s);
        l *= corr;
        u64 c2 = dup2(corr);
#pragma unroll
        for (int i = 0; i < 32; i++) acc2[i] = fmul2(acc2[i], c2);
        m = s;
    }
    float p = __expf(s - m);
    l += p;
    u64 p2 = dup2(p);
#pragma unroll
    for (int dd = 0; dd < 16; dd++) {
        ulonglong2 vv = *(const ulonglong2*)(vrow + dd * 4);
        acc2[2 * dd] = ffma2(p2, vv.x, acc2[2 * dd]);
        acc2[2 * dd + 1] = ffma2(p2, vv.y, acc2[2 * dd + 1]);
    }
}

__global__ __launch_bounds__(128) void gattn_partial(const float* __restrict__ mask) {
    int ks = blockIdx.x, h = blockIdx.y;
    int qi = threadIdx.x;
    __shared__ float Ks[GCH][HD];
    __shared__ float Vs[GCH][HD];
    __shared__ float Ms[GCH];

    u64 q2[32];
    const float* qp = g_Q + (size_t)qi * EMB + h * HD;
#pragma unroll
    for (int d2 = 0; d2 < 16; d2++) {
        ulonglong2 t2 = *(const ulonglong2*)(qp + d2 * 4);
        q2[2 * d2] = t2.x;
        q2[2 * d2 + 1] = t2.y;
    }
    float m = -1e30f, l = 0.f;
    u64 acc2[32];
#pragma unroll
    for (int i = 0; i < 32; i++) acc2[i] = 0ull;

    int kbase = ks * KPS;
    for (int c0 = 0; c0 < KPS; c0 += GCH) {
        __syncthreads();
        for (int i = threadIdx.x; i < GCH * (HD / 4); i += 128) {
            int r = i / (HD / 4), cc = (i % (HD / 4)) * 4;
            size_t off = (size_t)(kbase + c0 + r) * EMB + h * HD + cc;
            *(float4*)&Ks[r][cc] = *(const float4*)(g_K + off);
            *(float4*)&Vs[r][cc] = *(const float4*)(g_V + off);
        }
        if (threadIdx.x < GCH) {
            int x = kbase + c0 + threadIdx.x;
            Ms[threadIdx.x] = (x >= GL) ? mask[x - GL] : 0.f;
        }
        __syncthreads();
        for (int c = 0; c < GCH; c++) {
            float s = dot64(q2, &Ks[c][0]) + Ms[c];
            softmax_step(s, m, l, acc2, &Vs[c][0]);
        }
    }
    float* pp = g_part + (((size_t)h * KSPLIT + ks) * GL + qi) * (HD + 2);
    pp[0] = m;
    pp[1] = l;
#pragma unroll
    for (int dd = 0; dd < 16; dd++) {
        float2 x0 = up2(acc2[2 * dd]), x1 = up2(acc2[2 * dd + 1]);
        pp[2 + dd * 4 + 0] = x0.x;
        pp[2 + dd * 4 + 1] = x0.y;
        pp[2 + dd * 4 + 2] = x1.x;
        pp[2 + dd * 4 + 3] = x1.y;
    }
}

__global__ __launch_bounds__(128) void gattn_combine() {
    int h = blockIdx.x;
    int qi = threadIdx.x;
    float M = -1e30f;
    for (int ks = 0; ks < KSPLIT; ks++) {
        const float* pp = g_part + (((size_t)h * KSPLIT + ks) * GL + qi) * (HD + 2);
        M = fmaxf(M, pp[0]);
    }
    float L = 0.f;
    float out[HD];
#pragma unroll
    for (int d = 0; d < HD; d++) out[d] = 0.f;
    for (int ks = 0; ks < KSPLIT; ks++) {
        const float* pp = g_part + (((size_t)h * KSPLIT + ks) * GL + qi) * (HD + 2);
        float w = __expf(pp[0] - M);
        L += pp[1] * w;
#pragma unroll
        for (int d = 0; d < HD; d++) out[d] += pp[2 + d] * w;
    }
    float inv = 1.f / L;
    float* op = g_O + (size_t)(SEQ + qi) * EMB + h * HD;
#pragma unroll
    for (int d = 0; d < HD; d++) op[d] = out[d] * inv;
}

__global__ __launch_bounds__(128) void lattn(const float* __restrict__ mask) {
    int qt = blockIdx.x, n = blockIdx.y, h = blockIdx.z;
    int ti = threadIdx.x;
    __shared__ float Ks[LCH][HD];
    __shared__ float Vs[LCH][HD];
    __shared__ float Ms[LCH];

    int tokrow = n * BLK + qt * 128 + ti;
    int qrow = GL + tokrow;

    u64 q2[32];
    const float* qp = g_Q + (size_t)qrow * EMB + h * HD;
#pragma unroll
    for (int d2 = 0; d2 < 16; d2++) {
        ulonglong2 t2 = *(const ulonglong2*)(qp + d2 * 4);
        q2[2 * d2] = t2.x;
        q2[2 * d2 + 1] = t2.y;
    }
    float m = -1e30f, l = 0.f;
    u64 acc2[32];
#pragma unroll
    for (int i = 0; i < 32; i++) acc2[i] = 0ull;

    for (int c0 = 0; c0 < GL + BLK; c0 += LCH) {
        __syncthreads();
        for (int i = ti; i < LCH * (HD / 4); i += 128) {
            int r = i / (HD / 4), cc = (i % (HD / 4)) * 4;
            int x = c0 + r;
            int krow = (x < GL) ? x : (GL + n * BLK + (x - GL));
            size_t off = (size_t)krow * EMB + h * HD + cc;
            *(float4*)&Ks[r][cc] = *(const float4*)(g_K + off);
            *(float4*)&Vs[r][cc] = *(const float4*)(g_V + off);
        }
        if (ti < LCH) {
            int x = c0 + ti;
            Ms[ti] = (x >= GL) ? mask[n * BLK + x - GL] : 0.f;
        }
        __syncthreads();
        for (int c = 0; c < LCH; c++) {
            float s = dot64(q2, &Ks[c][0]) + Ms[c];
            softmax_step(s, m, l, acc2, &Vs[c][0]);
        }
    }
    float inv = 1.f / l;
    float* op = g_O + (size_t)tokrow * EMB + h * HD;
#pragma unroll
    for (int dd = 0; dd < 16; dd++) {
        float2 x0 = up2(acc2[2 * dd]), x1 = up2(acc2[2 * dd + 1]);
        float4 o;
        o.x = x0.x * inv; o.y = x0.y * inv;
        o.z = x1.x * inv; o.w = x1.y * inv;
        *(float4*)(op + dd * 4) = o;
    }
}

// ================= host =================
extern "C" void kernel_launch(void* const* d_in, const int* in_sizes, int n_in,
                              void* d_out, int out_size) {
    const float* tok = (const float*)d_in[0];
    const float* glob = (const float*)d_in[1];
    const float* mask = (const float*)d_in[2];
    const float* Wq = (const float*)d_in[3];
    const float* Wk = (const float*)d_in[4];
    const float* Wv = (const float*)d_in[5];
    const float* Wo = (const float*)d_in[6];
    float* out = (float*)d_out;

    __nv_bfloat16 *pXhi, *pXlo, *pWhi, *pWlo;
    float *pQ, *pK, *pV;
    cudaGetSymbolAddress((void**)&pXhi, g_Xhi);
    cudaGetSymbolAddress((void**)&pXlo, g_Xlo);
    cudaGetSymbolAddress((void**)&pWhi, g_Whi);
    cudaGetSymbolAddress((void**)&pWlo, g_Wlo);
    cudaGetSymbolAddress((void**)&pQ, g_Q);
    cudaGetSymbolAddress((void**)&pK, g_K);
    cudaGetSymbolAddress((void**)&pV, g_V);

    const float scaling = 0.125f;
    const size_t WSZ = (size_t)EMB * EMB;

    // 1. convert inputs
    {
        size_t tot4 = (size_t)LTOT * EMB / 4;
        cvt_x<<<(unsigned)((tot4 + 255) / 256), 256>>>((const float4*)glob, (const float4*)tok);
    }
    cvt_w<<<dim3(32, 32, 4), dim3(32, 8)>>>(Wq, Wk, Wv, Wo);

    // 2. projections (HMMA bf16 split)
    gemm_mma<<<dim3(8, LTOT / 128), 256>>>(pXhi, pXlo, pWhi + 0 * WSZ, pWlo + 0 * WSZ, pQ, scaling);
    gemm_mma<<<dim3(8, LTOT / 128), 256>>>(pXhi, pXlo, pWhi + 1 * WSZ, pWlo + 1 * WSZ, pK, 1.f);
    gemm_mma<<<dim3(8, LTOT / 128), 256>>>(pXhi, pXlo, pWhi + 2 * WSZ, pWlo + 2 * WSZ, pV, 1.f);

    // 3. attention
    gattn_partial<<<dim3(KSPLIT, NH), 128>>>(mask);
    gattn_combine<<<NH, 128>>>();
    lattn<<<dim3(4, NB, NH), 128>>>(mask);

    // 4. output projection: O rows [local; global] @ Wo -> d_out directly
    {
        size_t tot4 = (size_t)LTOT * EMB / 4;
        cvt_o<<<(unsigned)((tot4 + 255) / 256), 256>>>();
    }
    gemm_mma<<<dim3(8, LTOT / 128), 256>>>(pXhi, pXlo, pWhi + 3 * WSZ, pWlo + 3 * WSZ, out, 1.f);
}

// round 11
// speedup vs baseline: 3.3942x; 3.0495x over previous
#include <cuda_runtime.h>
#include <cuda_bf16.h>
#include <cstdint>

#define EMB 1024
#define NH 16
#define HD 64
#define SEQ 8192
#define GL 128
#define BLK 512
#define NB 16
#define LTOT 8320
#define GSPLIT 10
#define GTPS 13           // key tiles per global split (13*64*10 = 8320)

// ================= scratch =================
__device__ __nv_bfloat16 g_Xhi[(size_t)LTOT * EMB];
__device__ __nv_bfloat16 g_Xlo[(size_t)LTOT * EMB];
__device__ __nv_bfloat16 g_Whi[(size_t)4 * EMB * EMB];  // transposed [N,K]
__device__ __nv_bfloat16 g_Wlo[(size_t)4 * EMB * EMB];
__device__ __nv_bfloat16 g_Qhi[(size_t)LTOT * EMB];
__device__ __nv_bfloat16 g_Qlo[(size_t)LTOT * EMB];
__device__ __nv_bfloat16 g_Khi[(size_t)LTOT * EMB];
__device__ __nv_bfloat16 g_Klo[(size_t)LTOT * EMB];
__device__ __nv_bfloat16 g_Vhi[(size_t)LTOT * EMB];
__device__ __nv_bfloat16 g_Vlo[(size_t)LTOT * EMB];
__device__ float g_part[(size_t)NH * GSPLIT * GL * (HD + 2)];

// ================= PTX helpers (arch-neutral sm_80+) =================
__device__ __forceinline__ uint32_t smem_u32(const void* p) {
    uint32_t a;
    asm("{ .reg .u64 t; cvta.to.shared.u64 t, %1; cvt.u32.u64 %0, t; }" : "=r"(a) : "l"(p));
    return a;
}
__device__ __forceinline__ void cp16(uint32_t s, const void* g) {
    asm volatile("cp.async.cg.shared.global [%0], [%1], 16;" :: "r"(s), "l"(g));
}
#define CP_COMMIT() asm volatile("cp.async.commit_group;" ::: "memory")
#define CP_WAIT(n)  asm volatile("cp.async.wait_group %0;" :: "n"(n) : "memory")

#define LDSM_X4(r, addr)                                                          \
    asm volatile("ldmatrix.sync.aligned.m8n8.x4.shared.b16 {%0,%1,%2,%3},[%4];"   \
        : "=r"((r)[0]), "=r"((r)[1]), "=r"((r)[2]), "=r"((r)[3]) : "r"(addr))
#define LDSM_T4(r, addr)                                                          \
    asm volatile("ldmatrix.sync.aligned.m8n8.x4.trans.shared.b16 {%0,%1,%2,%3},[%4];" \
        : "=r"((r)[0]), "=r"((r)[1]), "=r"((r)[2]), "=r"((r)[3]) : "r"(addr))

#define MMA_BF16(c, a, b0v, b1v)                                                   \
    asm volatile("mma.sync.aligned.m16n8k16.row.col.f32.bf16.bf16.f32 "            \
        "{%0,%1,%2,%3},{%4,%5,%6,%7},{%8,%9},{%0,%1,%2,%3};"                       \
        : "+f"((c)[0]), "+f"((c)[1]), "+f"((c)[2]), "+f"((c)[3])                   \
        : "r"((a)[0]), "r"((a)[1]), "r"((a)[2]), "r"((a)[3]),                      \
          "r"(b0v), "r"(b1v))

// split a pair of floats into packed bf16x2 hi and lo words
__device__ __forceinline__ void split2(float x, float y, uint32_t& hi, uint32_t& lo) {
    __nv_bfloat16 hx = __float2bfloat16_rn(x), hy = __float2bfloat16_rn(y);
    __nv_bfloat16 lx = __float2bfloat16_rn(x - __bfloat162float(hx));
    __nv_bfloat16 ly = __float2bfloat16_rn(y - __bfloat162float(hy));
    __nv_bfloat162 h2 = __halves2bfloat162(hx, hy);
    __nv_bfloat162 l2 = __halves2bfloat162(lx, ly);
    hi = *(uint32_t*)&h2;
    lo = *(uint32_t*)&l2;
}
// pack two floats to bf16x2 hi + produce float residual pair packed
__device__ __forceinline__ uint32_t pack_bf2(float x, float y) {
    __nv_bfloat162 h2 = __halves2bfloat162(__float2bfloat16_rn(x), __float2bfloat16_rn(y));
    return *(uint32_t*)&h2;
}

// ================= conversion kernels =================
__global__ void cvt_x(const float4* __restrict__ glob, const float4* __restrict__ tok) {
    size_t i = (size_t)blockIdx.x * blockDim.x + threadIdx.x;
    size_t gl4 = (size_t)GL * EMB / 4, tot4 = (size_t)LTOT * EMB / 4;
    if (i >= tot4) return;
    float4 v = (i < gl4) ? glob[i] : tok[i - gl4];
    __nv_bfloat16 h[4], lo[4];
    float f[4] = {v.x, v.y, v.z, v.w};
#pragma unroll
    for (int j = 0; j < 4; j++) {
        h[j] = __float2bfloat16_rn(f[j]);
        lo[j] = __float2bfloat16_rn(f[j] - __bfloat162float(h[j]));
    }
    *(ushort4*)&g_Xhi[i * 4] = *(ushort4*)h;
    *(ushort4*)&g_Xlo[i * 4] = *(ushort4*)lo;
}

__global__ void cvt_w(const float* __restrict__ W0, const float* __restrict__ W1,
                      const float* __restrict__ W2, const float* __restrict__ W3) {
    __shared__ float s[32][33];
    int w = blockIdx.z;
    const float* W = (w == 0) ? W0 : (w == 1) ? W1 : (w == 2) ? W2 : W3;
    __nv_bfloat16* hi = g_Whi + ((size_t)w << 20);
    __nv_bfloat16* lo = g_Wlo + ((size_t)w << 20);
    int k0 = blockIdx.x * 32, n0 = blockIdx.y * 32;
    int tx = threadIdx.x, ty = threadIdx.y;
#pragma unroll
    for (int i = 0; i < 4; i++)
        s[ty + i * 8][tx] = W[(size_t)(k0 + ty + i * 8) * EMB + n0 + tx];
    __syncthreads();
#pragma unroll
    for (int i = 0; i < 4; i++) {
        float v = s[tx][ty + i * 8];
        __nv_bfloat16 h = __float2bfloat16_rn(v);
        size_t off = (size_t)(n0 + ty + i * 8) * EMB + k0 + tx;
        hi[off] = h;
        lo[off] = __float2bfloat16_rn(v - __bfloat162float(h));
    }
}

// ================= bf16 split-GEMM on mma.sync (proven R9) =================
// If Chi != nullptr: write bf16 hi/lo split outputs; else fp32 C.
__global__ __launch_bounds__(256, 2) void gemm_mma(
    const __nv_bfloat16* __restrict__ Ahi, const __nv_bfloat16* __restrict__ Alo,
    const __nv_bfloat16* __restrict__ Bhi, const __nv_bfloat16* __restrict__ Blo,
    float* __restrict__ C, float scale,
    __nv_bfloat16* __restrict__ Chi, __nv_bfloat16* __restrict__ Clo) {
    __shared__ __align__(128) __nv_bfloat16 As[2][128 * 32];
    __shared__ __align__(128) __nv_bfloat16 Bs[2][128 * 32];

    int t = threadIdx.x, lane = t & 31, wid = t >> 5;
    int wm = wid >> 1, wn = wid & 1;
    int m0 = blockIdx.y * 128, n0 = blockIdx.x * 128;

    uint32_t sA = smem_u32(As), sB = smem_u32(Bs);

    int khalfA = (lane >> 4) & 1;
    int rA = (lane & 7) + ((lane >> 3) & 1) * 8;
    int baseA[2], swA[2];
#pragma unroll
    for (int mt = 0; mt < 2; mt++) {
        int row = wm * 32 + mt * 16 + rA;
        baseA[mt] = row * 64;
        swA[mt] = (row >> 1) & 3;
    }
    int khalfB = (lane >> 3) & 1;
    int baseB[4], swB[4];
#pragma unroll
    for (int j = 0; j < 4; j++) {
        int row = wn * 64 + (2 * j + ((lane >> 4) & 1)) * 8 + (lane & 7);
        baseB[j] = row * 64;
        swB[j] = (row >> 1) & 3;
    }

    int ldr[2], ldso[2];
#pragma unroll
    for (int i = 0; i < 2; i++) {
        int idx = t + i * 256;
        int r = idx >> 2, ch = idx & 3;
        ldr[i] = r;
        ldso[i] = r * 64 + ((ch ^ ((r >> 1) & 3)) << 4);
    }
    int ldch[2] = {(t & 3) * 8, ((t + 256) & 3) * 8};

    float c[2][8][4];
#pragma unroll
    for (int mt = 0; mt < 2; mt++)
#pragma unroll
        for (int nt = 0; nt < 8; nt++)
#pragma unroll
            for (int k = 0; k < 4; k++) c[mt][nt][k] = 0.f;

#define LOAD_STAGE(kt, buf)                                                        \
    do {                                                                           \
        int p_ = (kt) >> 5;                                                        \
        int ksub_ = ((kt) & 31) * 32;                                              \
        const __nv_bfloat16* As_ = (p_ == 1) ? Alo : Ahi;                          \
        const __nv_bfloat16* Bs_ = (p_ == 2) ? Blo : Bhi;                          \
        _Pragma("unroll")                                                          \
        for (int i = 0; i < 2; i++) {                                              \
            cp16(sA + (buf) * 8192 + ldso[i],                                      \
                 As_ + (size_t)(m0 + ldr[i]) * EMB + ksub_ + ldch[i]);             \
            cp16(sB + (buf) * 8192 + ldso[i],                                      \
                 Bs_ + (size_t)(n0 + ldr[i]) * EMB + ksub_ + ldch[i]);             \
        }                                                                          \
        CP_COMMIT();                                                               \
    } while (0)

    LOAD_STAGE(0, 0);

    for (int kt = 0; kt < 96; kt++) {
        int buf = kt & 1;
        if (kt + 1 < 96) {
            LOAD_STAGE(kt + 1, (kt + 1) & 1);
            CP_WAIT(1);
        } else {
            CP_WAIT(0);
        }
        __syncthreads();

#pragma unroll
        for (int ks = 0; ks < 2; ks++) {
            uint32_t af[2][4], bf[8][2];
#pragma unroll
            for (int mt = 0; mt < 2; mt++) {
                uint32_t addr = sA + buf * 8192 + baseA[mt] +
                                (((ks * 2 + khalfA) ^ swA[mt]) << 4);
                LDSM_X4(af[mt], addr);
            }
#pragma unroll
            for (int j = 0; j < 4; j++) {
                uint32_t r[4];
                uint32_t addr = sB + buf * 8192 + baseB[j] +
                                (((ks * 2 + khalfB) ^ swB[j]) << 4);
                LDSM_X4(r, addr);
                bf[2 * j][0] = r[0]; bf[2 * j][1] = r[1];
                bf[2 * j + 1][0] = r[2]; bf[2 * j + 1][1] = r[3];
            }
#pragma unroll
            for (int mt = 0; mt < 2; mt++)
#pragma unroll
                for (int nt = 0; nt < 8; nt++)
                    MMA_BF16(c[mt][nt], af[mt], bf[nt][0], bf[nt][1]);
        }
        __syncthreads();
    }
#undef LOAD_STAGE

    int g = lane >> 2, tig = lane & 3;
#pragma unroll
    for (int mt = 0; mt < 2; mt++) {
#pragma unroll
        for (int nt = 0; nt < 8; nt++) {
            int row = m0 + wm * 32 + mt * 16 + g;
            int col = n0 + wn * 64 + nt * 8 + tig * 2;
            if (Chi) {
                uint32_t h0, l0, h1, l1;
                split2(c[mt][nt][0] * scale, c[mt][nt][1] * scale, h0, l0);
                split2(c[mt][nt][2] * scale, c[mt][nt][3] * scale, h1, l1);
                *(uint32_t*)(Chi + (size_t)row * EMB + col) = h0;
                *(uint32_t*)(Clo + (size_t)row * EMB + col) = l0;
                *(uint32_t*)(Chi + (size_t)(row + 8) * EMB + col) = h1;
                *(uint32_t*)(Clo + (size_t)(row + 8) * EMB + col) = l1;
            } else {
                float2 v0 = {c[mt][nt][0] * scale, c[mt][nt][1] * scale};
                float2 v1 = {c[mt][nt][2] * scale, c[mt][nt][3] * scale};
                *(float2*)(C + (size_t)row * EMB + col) = v0;
                *(float2*)(C + (size_t)(row + 8) * EMB + col) = v1;
            }
        }
    }
}

// ================= FA2-style attention on mma.sync =================
// MODE 0: local. grid (8 qtiles, 16 blocks, 16 heads). q rows = GL+n*512+qt*64.
//         KV tiles: 2 global tiles then 8 block tiles. Output: split to g_Xhi/lo.
// MODE 1: global partial. grid (2 qtiles, GSPLIT, 16 heads). q rows = qt*64.
//         KV tiles: 13 contiguous. Output: (m,l,acc) partial to g_part.
// Dynamic smem: 2 stages x { Khi 8K, Klo 8K, Vhi 8K, Vlo 8K, mask 256 } = 66048 B
#define STG 33024
template<int MODE>
__global__ __launch_bounds__(128, 2) void fmha(const float* __restrict__ mask) {
    extern __shared__ char smem[];
    int t = threadIdx.x, lane = t & 31, wid = t >> 5;
    int g = lane >> 2, tq = lane & 3;
    int h = blockIdx.z;
    int n = 0, ks = 0, qrow0;
    int NT;
    if (MODE == 0) {
        n = blockIdx.y;
        qrow0 = GL + n * BLK + blockIdx.x * 64 + wid * 16;
        NT = 10;
    } else {
        ks = blockIdx.y;
        qrow0 = blockIdx.x * 64 + wid * 16;
        NT = GTPS;
    }
    uint32_t sb = smem_u32(smem);

    // ---- load Q A-frags (hi & lo), 4 k-frags of d16 ----
    uint32_t qh[4][4], ql[4][4];
    {
        size_t r0 = (size_t)(qrow0 + g) * EMB + h * HD;
        size_t r1 = (size_t)(qrow0 + g + 8) * EMB + h * HD;
#pragma unroll
        for (int kf = 0; kf < 4; kf++) {
            int c0 = kf * 16 + 2 * tq, c1 = kf * 16 + 8 + 2 * tq;
            qh[kf][0] = *(const uint32_t*)(g_Qhi + r0 + c0);
            qh[kf][1] = *(const uint32_t*)(g_Qhi + r1 + c0);
            qh[kf][2] = *(const uint32_t*)(g_Qhi + r0 + c1);
            qh[kf][3] = *(const uint32_t*)(g_Qhi + r1 + c1);
            ql[kf][0] = *(const uint32_t*)(g_Qlo + r0 + c0);
            ql[kf][1] = *(const uint32_t*)(g_Qlo + r1 + c0);
            ql[kf][2] = *(const uint32_t*)(g_Qlo + r0 + c1);
            ql[kf][3] = *(const uint32_t*)(g_Qlo + r1 + c1);
        }
    }

    float m0 = -1e30f, m1 = -1e30f, l0 = 0.f, l1 = 0.f;
    float o[8][4];
#pragma unroll
    for (int i = 0; i < 8; i++)
#pragma unroll
        for (int j = 0; j < 4; j++) o[i][j] = 0.f;

#define ISSUE(tile, stage)                                                         \
    do {                                                                           \
        int krow0_ = (MODE == 0)                                                   \
            ? ((tile) < 2 ? (tile) * 64 : GL + n * BLK + ((tile) - 2) * 64)        \
            : (ks * GTPS + (tile)) * 64;                                           \
        uint32_t base_ = sb + (stage) * STG;                                       \
        _Pragma("unroll")                                                          \
        for (int rep = 0; rep < 4; rep++) {                                        \
            int idx = rep * 128 + t;                                               \
            int row = idx >> 3, ch = idx & 7;                                      \
            uint32_t so = row * 128 + ((ch ^ (row & 7)) << 4);                     \
            size_t go = (size_t)(krow0_ + row) * EMB + h * HD + ch * 8;            \
            cp16(base_ + so,          g_Khi + go);                                 \
            cp16(base_ + 8192 + so,   g_Klo + go);                                 \
            cp16(base_ + 16384 + so,  g_Vhi + go);                                 \
            cp16(base_ + 24576 + so,  g_Vlo + go);                                 \
        }                                                                          \
        CP_COMMIT();                                                               \
        if (t < 64) {                                                              \
            float mv;                                                              \
            if (MODE == 0) mv = ((tile) < 2) ? 0.f : mask[n * BLK + ((tile) - 2) * 64 + t]; \
            else { int x_ = krow0_ + t; mv = (x_ < GL) ? 0.f : mask[x_ - GL]; }    \
            *(float*)(smem + (stage) * STG + 32768 + t * 4) = mv;                  \
        }                                                                          \
    } while (0)

    ISSUE(0, 0);

    for (int tile = 0; tile < NT; tile++) {
        int stage = tile & 1;
        if (tile + 1 < NT) {
            ISSUE(tile + 1, stage ^ 1);
            CP_WAIT(1);
        } else {
            CP_WAIT(0);
        }
        __syncthreads();

        uint32_t Kh = sb + stage * STG, Kl = Kh + 8192;
        uint32_t Vh = Kh + 16384, Vl = Kh + 24576;
        const float* Ms = (const float*)(smem + stage * STG + 32768);

        // ---- scores: Qh*Kh + Ql*Kh + Qh*Kl ----
        float sc[8][4];
#pragma unroll
        for (int i = 0; i < 8; i++)
#pragma unroll
            for (int j = 0; j < 4; j++) sc[i][j] = 0.f;

        int kNtile = 2 * ((lane >> 4) & 1);  // helper bits for K ldmatrix
        int kKey7 = lane & 7;
        int kHalf = (lane >> 3) & 1;
#pragma unroll
        for (int kf = 0; kf < 4; kf++) {
            uint32_t kb[8][2];
#pragma unroll
            for (int j = 0; j < 4; j++) {
                uint32_t r[4];
                int key = (2 * j + (kNtile >> 1)) * 8 + kKey7;
                int chunk = kf * 2 + kHalf;
                uint32_t addr = Kh + key * 128 + ((chunk ^ (key & 7)) << 4);
                LDSM_X4(r, addr);
                kb[2 * j][0] = r[0]; kb[2 * j][1] = r[1];
                kb[2 * j + 1][0] = r[2]; kb[2 * j + 1][1] = r[3];
            }
#pragma unroll
            for (int nf = 0; nf < 8; nf++) MMA_BF16(sc[nf], qh[kf], kb[nf][0], kb[nf][1]);
#pragma unroll
            for (int nf = 0; nf < 8; nf++) MMA_BF16(sc[nf], ql[kf], kb[nf][0], kb[nf][1]);
#pragma unroll
            for (int j = 0; j < 4; j++) {
                uint32_t r[4];
                int key = (2 * j + (kNtile >> 1)) * 8 + kKey7;
                int chunk = kf * 2 + kHalf;
                uint32_t addr = Kl + key * 128 + ((chunk ^ (key & 7)) << 4);
                LDSM_X4(r, addr);
                kb[2 * j][0] = r[0]; kb[2 * j][1] = r[1];
                kb[2 * j + 1][0] = r[2]; kb[2 * j + 1][1] = r[3];
            }
#pragma unroll
            for (int nf = 0; nf < 8; nf++) MMA_BF16(sc[nf], qh[kf], kb[nf][0], kb[nf][1]);
        }

        // ---- mask + online softmax ----
        float rmax0 = -1e30f, rmax1 = -1e30f;
#pragma unroll
        for (int nf = 0; nf < 8; nf++) {
            float2 mv = *(const float2*)(Ms + nf * 8 + 2 * tq);
            sc[nf][0] += mv.x; sc[nf][1] += mv.y;
            sc[nf][2] += mv.x; sc[nf][3] += mv.y;
            rmax0 = fmaxf(rmax0, fmaxf(sc[nf][0], sc[nf][1]));
            rmax1 = fmaxf(rmax1, fmaxf(sc[nf][2], sc[nf][3]));
        }
        rmax0 = fmaxf(rmax0, __shfl_xor_sync(0xffffffffu, rmax0, 1));
        rmax0 = fmaxf(rmax0, __shfl_xor_sync(0xffffffffu, rmax0, 2));
        rmax1 = fmaxf(rmax1, __shfl_xor_sync(0xffffffffu, rmax1, 1));
        rmax1 = fmaxf(rmax1, __shfl_xor_sync(0xffffffffu, rmax1, 2));
        float mn0 = fmaxf(m0, rmax0), mn1 = fmaxf(m1, rmax1);
        float corr0 = __expf(m0 - mn0), corr1 = __expf(m1 - mn1);
        m0 = mn0; m1 = mn1;
#pragma unroll
        for (int nf = 0; nf < 8; nf++) {
            o[nf][0] *= corr0; o[nf][1] *= corr0;
            o[nf][2] *= corr1; o[nf][3] *= corr1;
        }
        float rs0 = 0.f, rs1 = 0.f;
#pragma unroll
        for (int nf = 0; nf < 8; nf++) {
            sc[nf][0] = __expf(sc[nf][0] - m0);
            sc[nf][1] = __expf(sc[nf][1] - m0);
            sc[nf][2] = __expf(sc[nf][2] - m1);
            sc[nf][3] = __expf(sc[nf][3] - m1);
            rs0 += sc[nf][0] + sc[nf][1];
            rs1 += sc[nf][2] + sc[nf][3];
        }
        rs0 += __shfl_xor_sync(0xffffffffu, rs0, 1);
        rs0 += __shfl_xor_sync(0xffffffffu, rs0, 2);
        rs1 += __shfl_xor_sync(0xffffffffu, rs1, 1);
        rs1 += __shfl_xor_sync(0xffffffffu, rs1, 2);
        l0 = l0 * corr0 + rs0;
        l1 = l1 * corr1 + rs1;

        // ---- build P A-frags (hi & lo) from score frags ----
        uint32_t ph[4][4], pl[4][4];
#pragma unroll
        for (int kk = 0; kk < 4; kk++) {
            float* s0 = sc[2 * kk];
            float* s1 = sc[2 * kk + 1];
            ph[kk][0] = pack_bf2(s0[0], s0[1]);
            ph[kk][1] = pack_bf2(s0[2], s0[3]);
            ph[kk][2] = pack_bf2(s1[0], s1[1]);
            ph[kk][3] = pack_bf2(s1[2], s1[3]);
            __nv_bfloat162 b;
            b = *(__nv_bfloat162*)&ph[kk][0];
            pl[kk][0] = pack_bf2(s0[0] - __bfloat162float(b.x), s0[1] - __bfloat162float(b.y));
            b = *(__nv_bfloat162*)&ph[kk][1];
            pl[kk][1] = pack_bf2(s0[2] - __bfloat162float(b.x), s0[3] - __bfloat162float(b.y));
            b = *(__nv_bfloat162*)&ph[kk][2];
            pl[kk][2] = pack_bf2(s1[0] - __bfloat162float(b.x), s1[1] - __bfloat162float(b.y));
            b = *(__nv_bfloat162*)&ph[kk][3];
            pl[kk][3] = pack_bf2(s1[2] - __bfloat162float(b.x), s1[3] - __bfloat162float(b.y));
        }

        // ---- PV: Ph*Vh + Pl*Vh + Ph*Vl, V frags via ldmatrix.trans ----
        int grp = lane >> 3;
#pragma unroll
        for (int kk = 0; kk < 4; kk++) {
#pragma unroll
            for (int j = 0; j < 4; j++) {
                int key = kk * 16 + (grp & 1) * 8 + (lane & 7);
                int dchunk = j * 2 + (grp >> 1);
                uint32_t soff = key * 128 + ((dchunk ^ (key & 7)) << 4);
                uint32_t r[4];
                LDSM_T4(r, Vh + soff);
                MMA_BF16(o[2 * j], ph[kk], r[0], r[1]);
                MMA_BF16(o[2 * j + 1], ph[kk], r[2], r[3]);
                MMA_BF16(o[2 * j], pl[kk], r[0], r[1]);
                MMA_BF16(o[2 * j + 1], pl[kk], r[2], r[3]);
                LDSM_T4(r, Vl + soff);
                MMA_BF16(o[2 * j], ph[kk], r[0], r[1]);
                MMA_BF16(o[2 * j + 1], ph[kk], r[2], r[3]);
            }
        }
        __syncthreads();
    }
#undef ISSUE

    // ---- epilogue ----
    if (MODE == 0) {
        float inv0 = 1.f / l0, inv1 = 1.f / l1;
        int row0 = qrow0 - GL + g;          // token row
        int row1 = row0 + 8;
#pragma unroll
        for (int nf = 0; nf < 8; nf++) {
            int col = h * HD + nf * 8 + 2 * tq;
            uint32_t h0, lo0, h1, lo1;
            split2(o[nf][0] * inv0, o[nf][1] * inv0, h0, lo0);
            split2(o[nf][2] * inv1, o[nf][3] * inv1, h1, lo1);
            *(uint32_t*)(g_Xhi + (size_t)row0 * EMB + col) = h0;
            *(uint32_t*)(g_Xlo + (size_t)row0 * EMB + col) = lo0;
            *(uint32_t*)(g_Xhi + (size_t)row1 * EMB + col) = h1;
            *(uint32_t*)(g_Xlo + (size_t)row1 * EMB + col) = lo1;
        }
    } else {
        int qi0 = qrow0 + g;                // global q index 0..127
        float* pp0 = g_part + (((size_t)h * GSPLIT + ks) * GL + qi0) * (HD + 2);
        float* pp1 = g_part + (((size_t)h * GSPLIT + ks) * GL + qi0 + 8) * (HD + 2);
        if (tq == 0) {
            pp0[0] = m0; pp0[1] = l0;
            pp1[0] = m1; pp1[1] = l1;
        }
#pragma unroll
        for (int nf = 0; nf < 8; nf++) {
            int col = nf * 8 + 2 * tq;
            pp0[2 + col] = o[nf][0]; pp0[2 + col + 1] = o[nf][1];
            pp1[2 + col] = o[nf][2]; pp1[2 + col + 1] = o[nf][3];
        }
    }
}

// ================= combine global-attn partials (split output) =================
__global__ __launch_bounds__(128) void gattn_combine() {
    int h = blockIdx.x;
    int qi = threadIdx.x;
    float M = -1e30f;
    for (int ks = 0; ks < GSPLIT; ks++) {
        const float* pp = g_part + (((size_t)h * GSPLIT + ks) * GL + qi) * (HD + 2);
        M = fmaxf(M, pp[0]);
    }
    float L = 0.f;
    float out[HD];
#pragma unroll
    for (int d = 0; d < HD; d++) out[d] = 0.f;
    for (int ks = 0; ks < GSPLIT; ks++) {
        const float* pp = g_part + (((size_t)h * GSPLIT + ks) * GL + qi) * (HD + 2);
        float w = __expf(pp[0] - M);
        L += pp[1] * w;
#pragma unroll
        for (int d = 0; d < HD; d++) out[d] += pp[2 + d] * w;
    }
    float inv = 1.f / L;
    size_t rbase = (size_t)(SEQ + qi) * EMB + h * HD;
#pragma unroll
    for (int d = 0; d < HD; d += 2) {
        uint32_t hw, lw;
        split2(out[d] * inv, out[d + 1] * inv, hw, lw);
        *(uint32_t*)(g_Xhi + rbase + d) = hw;
        *(uint32_t*)(g_Xlo + rbase + d) = lw;
    }
}

// ================= host =================
extern "C" void kernel_launch(void* const* d_in, const int* in_sizes, int n_in,
                              void* d_out, int out_size) {
    const float* tok = (const float*)d_in[0];
    const float* glob = (const float*)d_in[1];
    const float* mask = (const float*)d_in[2];
    const float* Wq = (const float*)d_in[3];
    const float* Wk = (const float*)d_in[4];
    const float* Wv = (const float*)d_in[5];
    const float* Wo = (const float*)d_in[6];
    float* out = (float*)d_out;

    __nv_bfloat16 *pXhi, *pXlo, *pWhi, *pWlo;
    __nv_bfloat16 *pQhi, *pQlo, *pKhi, *pKlo, *pVhi, *pVlo;
    cudaGetSymbolAddress((void**)&pXhi, g_Xhi);
    cudaGetSymbolAddress((void**)&pXlo, g_Xlo);
    cudaGetSymbolAddress((void**)&pWhi, g_Whi);
    cudaGetSymbolAddress((void**)&pWlo, g_Wlo);
    cudaGetSymbolAddress((void**)&pQhi, g_Qhi);
    cudaGetSymbolAddress((void**)&pQlo, g_Qlo);
    cudaGetSymbolAddress((void**)&pKhi, g_Khi);
    cudaGetSymbolAddress((void**)&pKlo, g_Klo);
    cudaGetSymbolAddress((void**)&pVhi, g_Vhi);
    cudaGetSymbolAddress((void**)&pVlo, g_Vlo);

    static bool attr_done = false;
    if (!attr_done) {
        cudaFuncSetAttribute(fmha<0>, cudaFuncAttributeMaxDynamicSharedMemorySize, 2 * STG);
        cudaFuncSetAttribute(fmha<1>, cudaFuncAttributeMaxDynamicSharedMemorySize, 2 * STG);
        attr_done = true;
    }

    const float scaling = 0.125f;
    const size_t WSZ = (size_t)EMB * EMB;

    // 1. convert inputs
    {
        size_t tot4 = (size_t)LTOT * EMB / 4;
        cvt_x<<<(unsigned)((tot4 + 255) / 256), 256>>>((const float4*)glob, (const float4*)tok);
    }
    cvt_w<<<dim3(32, 32, 4), dim3(32, 8)>>>(Wq, Wk, Wv, Wo);

    // 2. projections -> split bf16 Q/K/V
    gemm_mma<<<dim3(8, LTOT / 128), 256>>>(pXhi, pXlo, pWhi, pWlo, nullptr, scaling, pQhi, pQlo);
    gemm_mma<<<dim3(8, LTOT / 128), 256>>>(pXhi, pXlo, pWhi + WSZ, pWlo + WSZ, nullptr, 1.f, pKhi, pKlo);
    gemm_mma<<<dim3(8, LTOT / 128), 256>>>(pXhi, pXlo, pWhi + 2 * WSZ, pWlo + 2 * WSZ, nullptr, 1.f, pVhi, pVlo);

    // 3. attention (HMMA flash) -> writes g_Xhi/g_Xlo [local rows 0..8191, global rows 8192..]
    fmha<1><<<dim3(2, GSPLIT, NH), 128, 2 * STG>>>(mask);
    gattn_combine<<<NH, 128>>>();
    fmha<0><<<dim3(8, NB, NH), 128, 2 * STG>>>(mask);

    // 4. output projection: [l_out; g_out] @ Wo -> d_out
    gemm_mma<<<dim3(8, LTOT / 128), 256>>>(pXhi, pXlo, pWhi + 3 * WSZ, pWlo + 3 * WSZ, out, 1.f, nullptr, nullptr);
}

// round 12
// speedup vs baseline: 3.6010x; 1.0609x over previous
#include <cuda_runtime.h>
#include <cuda_bf16.h>
#include <cstdint>

#define EMB 1024
#define NH 16
#define HD 64
#define SEQ 8192
#define GL 128
#define BLK 512
#define NB 16
#define LTOT 8320
#define GSPLIT 10
#define GTPS 13

// ================= scratch =================
__device__ __nv_bfloat16 g_Xhi[(size_t)LTOT * EMB];
__device__ __nv_bfloat16 g_Xlo[(size_t)LTOT * EMB];
__device__ __nv_bfloat16 g_Whi[(size_t)4 * EMB * EMB];  // transposed [N,K]
__device__ __nv_bfloat16 g_Wlo[(size_t)4 * EMB * EMB];
__device__ __nv_bfloat16 g_Qhi[(size_t)LTOT * EMB];
__device__ __nv_bfloat16 g_Qlo[(size_t)LTOT * EMB];
__device__ __nv_bfloat16 g_Khi[(size_t)LTOT * EMB];
__device__ __nv_bfloat16 g_Klo[(size_t)LTOT * EMB];
__device__ __nv_bfloat16 g_Vhi[(size_t)LTOT * EMB];
__device__ __nv_bfloat16 g_Vlo[(size_t)LTOT * EMB];
__device__ float g_part[(size_t)NH * GSPLIT * GL * (HD + 2)];

// ================= PTX helpers =================
__device__ __forceinline__ uint32_t smem_u32(const void* p) {
    uint32_t a;
    asm("{ .reg .u64 t; cvta.to.shared.u64 t, %1; cvt.u32.u64 %0, t; }" : "=r"(a) : "l"(p));
    return a;
}
__device__ __forceinline__ void cp16(uint32_t s, const void* g) {
    asm volatile("cp.async.cg.shared.global [%0], [%1], 16;" :: "r"(s), "l"(g));
}
#define CP_COMMIT() asm volatile("cp.async.commit_group;" ::: "memory")
#define CP_WAIT(n)  asm volatile("cp.async.wait_group %0;" :: "n"(n) : "memory")

#define LDSM_X4(r, addr)                                                          \
    asm volatile("ldmatrix.sync.aligned.m8n8.x4.shared.b16 {%0,%1,%2,%3},[%4];"   \
        : "=r"((r)[0]), "=r"((r)[1]), "=r"((r)[2]), "=r"((r)[3]) : "r"(addr))
#define LDSM_T4(r, addr)                                                          \
    asm volatile("ldmatrix.sync.aligned.m8n8.x4.trans.shared.b16 {%0,%1,%2,%3},[%4];" \
        : "=r"((r)[0]), "=r"((r)[1]), "=r"((r)[2]), "=r"((r)[3]) : "r"(addr))

#define MMA_BF16(c, a, b0v, b1v)                                                   \
    asm volatile("mma.sync.aligned.m16n8k16.row.col.f32.bf16.bf16.f32 "            \
        "{%0,%1,%2,%3},{%4,%5,%6,%7},{%8,%9},{%0,%1,%2,%3};"                       \
        : "+f"((c)[0]), "+f"((c)[1]), "+f"((c)[2]), "+f"((c)[3])                   \
        : "r"((a)[0]), "r"((a)[1]), "r"((a)[2]), "r"((a)[3]),                      \
          "r"(b0v), "r"(b1v))

__device__ __forceinline__ void split2(float x, float y, uint32_t& hi, uint32_t& lo) {
    __nv_bfloat16 hx = __float2bfloat16_rn(x), hy = __float2bfloat16_rn(y);
    __nv_bfloat16 lx = __float2bfloat16_rn(x - __bfloat162float(hx));
    __nv_bfloat16 ly = __float2bfloat16_rn(y - __bfloat162float(hy));
    __nv_bfloat162 h2 = __halves2bfloat162(hx, hy);
    __nv_bfloat162 l2 = __halves2bfloat162(lx, ly);
    hi = *(uint32_t*)&h2;
    lo = *(uint32_t*)&l2;
}
__device__ __forceinline__ uint32_t pack_bf2(float x, float y) {
    __nv_bfloat162 h2 = __halves2bfloat162(__float2bfloat16_rn(x), __float2bfloat16_rn(y));
    return *(uint32_t*)&h2;
}

// ================= conversion kernels =================
__global__ void cvt_x(const float4* __restrict__ glob, const float4* __restrict__ tok) {
    size_t i = (size_t)blockIdx.x * blockDim.x + threadIdx.x;
    size_t gl4 = (size_t)GL * EMB / 4, tot4 = (size_t)LTOT * EMB / 4;
    if (i >= tot4) return;
    float4 v = (i < gl4) ? glob[i] : tok[i - gl4];
    __nv_bfloat16 h[4], lo[4];
    float f[4] = {v.x, v.y, v.z, v.w};
#pragma unroll
    for (int j = 0; j < 4; j++) {
        h[j] = __float2bfloat16_rn(f[j]);
        lo[j] = __float2bfloat16_rn(f[j] - __bfloat162float(h[j]));
    }
    *(ushort4*)&g_Xhi[i * 4] = *(ushort4*)h;
    *(ushort4*)&g_Xlo[i * 4] = *(ushort4*)lo;
}

__global__ void cvt_w(const float* __restrict__ W0, const float* __restrict__ W1,
                      const float* __restrict__ W2, const float* __restrict__ W3) {
    __shared__ float s[32][33];
    int w = blockIdx.z;
    const float* W = (w == 0) ? W0 : (w == 1) ? W1 : (w == 2) ? W2 : W3;
    __nv_bfloat16* hi = g_Whi + ((size_t)w << 20);
    __nv_bfloat16* lo = g_Wlo + ((size_t)w << 20);
    int k0 = blockIdx.x * 32, n0 = blockIdx.y * 32;
    int tx = threadIdx.x, ty = threadIdx.y;
#pragma unroll
    for (int i = 0; i < 4; i++)
        s[ty + i * 8][tx] = W[(size_t)(k0 + ty + i * 8) * EMB + n0 + tx];
    __syncthreads();
#pragma unroll
    for (int i = 0; i < 4; i++) {
        float v = s[tx][ty + i * 8];
        __nv_bfloat16 h = __float2bfloat16_rn(v);
        size_t off = (size_t)(n0 + ty + i * 8) * EMB + k0 + tx;
        hi[off] = h;
        lo[off] = __float2bfloat16_rn(v - __bfloat162float(h));
    }
}

// ================= bf16 split-GEMM core (4-stage, single sync) =================
// stage layout: [A 8192 | B 8192] x 4 stages = 65536 B dynamic smem
__device__ __forceinline__ void gload(uint32_t sbase,
    const __nv_bfloat16* __restrict__ Asrc, const __nv_bfloat16* __restrict__ Bsrc,
    int m0, int n0, int ksub, const int* ldr, const int* ldso, const int* ldch) {
#pragma unroll
    for (int i = 0; i < 2; i++) {
        cp16(sbase + ldso[i], Asrc + (size_t)(m0 + ldr[i]) * EMB + ksub + ldch[i]);
        cp16(sbase + 8192 + ldso[i], Bsrc + (size_t)(n0 + ldr[i]) * EMB + ksub + ldch[i]);
    }
}

__device__ __forceinline__ void gemm_core(
    const __nv_bfloat16* __restrict__ Ahi, const __nv_bfloat16* __restrict__ Alo,
    const __nv_bfloat16* __restrict__ Bhi, const __nv_bfloat16* __restrict__ Blo,
    float* __restrict__ C, float scale,
    __nv_bfloat16* __restrict__ Chi, __nv_bfloat16* __restrict__ Clo,
    int m0, int n0, char* gsm) {

    int t = threadIdx.x, lane = t & 31, wid = t >> 5;
    int wm = wid >> 1, wn = wid & 1;
    uint32_t sb = smem_u32(gsm);

    int khalfA = (lane >> 4) & 1;
    int rA = (lane & 7) + ((lane >> 3) & 1) * 8;
    int baseA[2], swA[2];
#pragma unroll
    for (int mt = 0; mt < 2; mt++) {
        int row = wm * 32 + mt * 16 + rA;
        baseA[mt] = row * 64;
        swA[mt] = (row >> 1) & 3;
    }
    int khalfB = (lane >> 3) & 1;
    int baseB[4], swB[4];
#pragma unroll
    for (int j = 0; j < 4; j++) {
        int row = wn * 64 + (2 * j + ((lane >> 4) & 1)) * 8 + (lane & 7);
        baseB[j] = row * 64;
        swB[j] = (row >> 1) & 3;
    }

    int ldr[2], ldso[2], ldch[2];
#pragma unroll
    for (int i = 0; i < 2; i++) {
        int idx = t + i * 256;
        int r = idx >> 2, ch = idx & 3;
        ldr[i] = r;
        ldso[i] = r * 64 + ((ch ^ ((r >> 1) & 3)) << 4);
        ldch[i] = ch * 8;
    }

    float c[2][8][4];
#pragma unroll
    for (int mt = 0; mt < 2; mt++)
#pragma unroll
        for (int nt = 0; nt < 8; nt++)
#pragma unroll
            for (int k = 0; k < 4; k++) c[mt][nt][k] = 0.f;

    // prologue: stages 0..2 (all phase 0)
#pragma unroll
    for (int s = 0; s < 3; s++) {
        gload(sb + s * 16384, Ahi, Bhi, m0, n0, s * 32, ldr, ldso, ldch);
        CP_COMMIT();
    }

    for (int kt = 0; kt < 96; kt++) {
        CP_WAIT(2);
        __syncthreads();
        int kn = kt + 3;
        if (kn < 96) {
            int p = kn >> 5, ksub = (kn & 31) * 32;
            gload(sb + (kn & 3) * 16384,
                  (p == 1) ? Alo : Ahi, (p == 2) ? Blo : Bhi,
                  m0, n0, ksub, ldr, ldso, ldch);
        }
        CP_COMMIT();

        uint32_t bb = sb + (kt & 3) * 16384;
#pragma unroll
        for (int ks = 0; ks < 2; ks++) {
            uint32_t af[2][4], bf[8][2];
#pragma unroll
            for (int mt = 0; mt < 2; mt++) {
                uint32_t addr = bb + baseA[mt] + (((ks * 2 + khalfA) ^ swA[mt]) << 4);
                LDSM_X4(af[mt], addr);
            }
#pragma unroll
            for (int j = 0; j < 4; j++) {
                uint32_t r[4];
                uint32_t addr = bb + 8192 + baseB[j] + (((ks * 2 + khalfB) ^ swB[j]) << 4);
                LDSM_X4(r, addr);
                bf[2 * j][0] = r[0]; bf[2 * j][1] = r[1];
                bf[2 * j + 1][0] = r[2]; bf[2 * j + 1][1] = r[3];
            }
#pragma unroll
            for (int mt = 0; mt < 2; mt++)
#pragma unroll
                for (int nt = 0; nt < 8; nt++)
                    MMA_BF16(c[mt][nt], af[mt], bf[nt][0], bf[nt][1]);
        }
    }

    int g = lane >> 2, tig = lane & 3;
#pragma unroll
    for (int mt = 0; mt < 2; mt++) {
#pragma unroll
        for (int nt = 0; nt < 8; nt++) {
            int row = m0 + wm * 32 + mt * 16 + g;
            int col = n0 + wn * 64 + nt * 8 + tig * 2;
            if (Chi) {
                uint32_t h0, l0, h1, l1;
                split2(c[mt][nt][0] * scale, c[mt][nt][1] * scale, h0, l0);
                split2(c[mt][nt][2] * scale, c[mt][nt][3] * scale, h1, l1);
                *(uint32_t*)(Chi + (size_t)row * EMB + col) = h0;
                *(uint32_t*)(Clo + (size_t)row * EMB + col) = l0;
                *(uint32_t*)(Chi + (size_t)(row + 8) * EMB + col) = h1;
                *(uint32_t*)(Clo + (size_t)(row + 8) * EMB + col) = l1;
            } else {
                float2 v0 = {c[mt][nt][0] * scale, c[mt][nt][1] * scale};
                float2 v1 = {c[mt][nt][2] * scale, c[mt][nt][3] * scale};
                *(float2*)(C + (size_t)row * EMB + col) = v0;
                *(float2*)(C + (size_t)(row + 8) * EMB + col) = v1;
            }
        }
    }
}

// merged Q/K/V projection: grid (24, 65). w = bx>>3 selects weight/output.
__global__ __launch_bounds__(256, 2) void gemm_qkv() {
    extern __shared__ __align__(128) char gsm[];
    int w = blockIdx.x >> 3;
    int n0 = (blockIdx.x & 7) * 128;
    int m0 = blockIdx.y * 128;
    const size_t WSZ = (size_t)EMB * EMB;
    __nv_bfloat16* Chi = (w == 0) ? g_Qhi : (w == 1) ? g_Khi : g_Vhi;
    __nv_bfloat16* Clo = (w == 0) ? g_Qlo : (w == 1) ? g_Klo : g_Vlo;
    float scale = (w == 0) ? 0.125f : 1.f;
    gemm_core(g_Xhi, g_Xlo, g_Whi + w * WSZ, g_Wlo + w * WSZ,
              nullptr, scale, Chi, Clo, m0, n0, gsm);
}

// output projection: grid (8, 65), fp32 out
__global__ __launch_bounds__(256, 2) void gemm_wo(float* __restrict__ C) {
    extern __shared__ __align__(128) char gsm[];
    const size_t WSZ = (size_t)EMB * EMB;
    gemm_core(g_Xhi, g_Xlo, g_Whi + 3 * WSZ, g_Wlo + 3 * WSZ,
              C, 1.f, nullptr, nullptr, blockIdx.y * 128, blockIdx.x * 128, gsm);
}

// ================= FA2-style attention (3-stage, single sync) =================
#define STG 33024
template<int MODE>
__global__ __launch_bounds__(128, 2) void fmha(const float* __restrict__ mask) {
    extern __shared__ __align__(128) char smem[];
    int t = threadIdx.x, lane = t & 31, wid = t >> 5;
    int g = lane >> 2, tq = lane & 3;
    int h = blockIdx.z;
    int n = 0, ks = 0, qrow0;
    int NT;
    if (MODE == 0) {
        n = blockIdx.y;
        qrow0 = GL + n * BLK + blockIdx.x * 64 + wid * 16;
        NT = 10;
    } else {
        ks = blockIdx.y;
        qrow0 = blockIdx.x * 64 + wid * 16;
        NT = GTPS;
    }
    uint32_t sb = smem_u32(smem);

    uint32_t qh[4][4], ql[4][4];
    {
        size_t r0 = (size_t)(qrow0 + g) * EMB + h * HD;
        size_t r1 = (size_t)(qrow0 + g + 8) * EMB + h * HD;
#pragma unroll
        for (int kf = 0; kf < 4; kf++) {
            int c0 = kf * 16 + 2 * tq, c1 = kf * 16 + 8 + 2 * tq;
            qh[kf][0] = *(const uint32_t*)(g_Qhi + r0 + c0);
            qh[kf][1] = *(const uint32_t*)(g_Qhi + r1 + c0);
            qh[kf][2] = *(const uint32_t*)(g_Qhi + r0 + c1);
            qh[kf][3] = *(const uint32_t*)(g_Qhi + r1 + c1);
            ql[kf][0] = *(const uint32_t*)(g_Qlo + r0 + c0);
            ql[kf][1] = *(const uint32_t*)(g_Qlo + r1 + c0);
            ql[kf][2] = *(const uint32_t*)(g_Qlo + r0 + c1);
            ql[kf][3] = *(const uint32_t*)(g_Qlo + r1 + c1);
        }
    }

    float m0 = -1e30f, m1 = -1e30f, l0 = 0.f, l1 = 0.f;
    float o[8][4];
#pragma unroll
    for (int i = 0; i < 8; i++)
#pragma unroll
        for (int j = 0; j < 4; j++) o[i][j] = 0.f;

#define ISSUE(tile, stage)                                                         \
    do {                                                                           \
        int krow0_ = (MODE == 0)                                                   \
            ? ((tile) < 2 ? (tile) * 64 : GL + n * BLK + ((tile) - 2) * 64)        \
            : (ks * GTPS + (tile)) * 64;                                           \
        uint32_t base_ = sb + (stage) * STG;                                       \
        _Pragma("unroll")                                                          \
        for (int rep = 0; rep < 4; rep++) {                                        \
            int idx = rep * 128 + t;                                               \
            int row = idx >> 3, ch = idx & 7;                                      \
            uint32_t so = row * 128 + ((ch ^ (row & 7)) << 4);                     \
            size_t go = (size_t)(krow0_ + row) * EMB + h * HD + ch * 8;            \
            cp16(base_ + so,          g_Khi + go);                                 \
            cp16(base_ + 8192 + so,   g_Klo + go);                                 \
            cp16(base_ + 16384 + so,  g_Vhi + go);                                 \
            cp16(base_ + 24576 + so,  g_Vlo + go);                                 \
        }                                                                          \
        if (t < 64) {                                                              \
            float mv;                                                              \
            if (MODE == 0) mv = ((tile) < 2) ? 0.f : mask[n * BLK + ((tile) - 2) * 64 + t]; \
            else { int x_ = krow0_ + t; mv = (x_ < GL) ? 0.f : mask[x_ - GL]; }    \
            *(float*)(smem + (stage) * STG + 32768 + t * 4) = mv;                  \
        }                                                                          \
    } while (0)

    ISSUE(0, 0); CP_COMMIT();
    ISSUE(1, 1); CP_COMMIT();

    for (int tile = 0; tile < NT; tile++) {
        int stage = tile % 3;
        CP_WAIT(1);
        __syncthreads();
        if (tile + 2 < NT) ISSUE(tile + 2, (tile + 2) % 3);
        CP_COMMIT();

        uint32_t Kh = sb + stage * STG, Kl = Kh + 8192;
        uint32_t Vh = Kh + 16384, Vl = Kh + 24576;
        const float* Ms = (const float*)(smem + stage * STG + 32768);

        float sc[8][4];
#pragma unroll
        for (int i = 0; i < 8; i++)
#pragma unroll
            for (int j = 0; j < 4; j++) sc[i][j] = 0.f;

        int kNtile = 2 * ((lane >> 4) & 1);
        int kKey7 = lane & 7;
        int kHalf = (lane >> 3) & 1;
#pragma unroll
        for (int kf = 0; kf < 4; kf++) {
            uint32_t kb[8][2];
#pragma unroll
            for (int j = 0; j < 4; j++) {
                uint32_t r[4];
                int key = (2 * j + (kNtile >> 1)) * 8 + kKey7;
                int chunk = kf * 2 + kHalf;
                uint32_t addr = Kh + key * 128 + ((chunk ^ (key & 7)) << 4);
                LDSM_X4(r, addr);
                kb[2 * j][0] = r[0]; kb[2 * j][1] = r[1];
                kb[2 * j + 1][0] = r[2]; kb[2 * j + 1][1] = r[3];
            }
#pragma unroll
            for (int nf = 0; nf < 8; nf++) MMA_BF16(sc[nf], qh[kf], kb[nf][0], kb[nf][1]);
#pragma unroll
            for (int nf = 0; nf < 8; nf++) MMA_BF16(sc[nf], ql[kf], kb[nf][0], kb[nf][1]);
#pragma unroll
            for (int j = 0; j < 4; j++) {
                uint32_t r[4];
                int key = (2 * j + (kNtile >> 1)) * 8 + kKey7;
                int chunk = kf * 2 + kHalf;
                uint32_t addr = Kl + key * 128 + ((chunk ^ (key & 7)) << 4);
                LDSM_X4(r, addr);
                kb[2 * j][0] = r[0]; kb[2 * j][1] = r[1];
                kb[2 * j + 1][0] = r[2]; kb[2 * j + 1][1] = r[3];
            }
#pragma unroll
            for (int nf = 0; nf < 8; nf++) MMA_BF16(sc[nf], qh[kf], kb[nf][0], kb[nf][1]);
        }

        float rmax0 = -1e30f, rmax1 = -1e30f;
#pragma unroll
        for (int nf = 0; nf < 8; nf++) {
            float2 mv = *(const float2*)(Ms + nf * 8 + 2 * tq);
            sc[nf][0] += mv.x; sc[nf][1] += mv.y;
            sc[nf][2] += mv.x; sc[nf][3] += mv.y;
            rmax0 = fmaxf(rmax0, fmaxf(sc[nf][0], sc[nf][1]));
            rmax1 = fmaxf(rmax1, fmaxf(sc[nf][2], sc[nf][3]));
        }
        rmax0 = fmaxf(rmax0, __shfl_xor_sync(0xffffffffu, rmax0, 1));
        rmax0 = fmaxf(rmax0, __shfl_xor_sync(0xffffffffu, rmax0, 2));
        rmax1 = fmaxf(rmax1, __shfl_xor_sync(0xffffffffu, rmax1, 1));
        rmax1 = fmaxf(rmax1, __shfl_xor_sync(0xffffffffu, rmax1, 2));
        float mn0 = fmaxf(m0, rmax0), mn1 = fmaxf(m1, rmax1);
        float corr0 = __expf(m0 - mn0), corr1 = __expf(m1 - mn1);
        m0 = mn0; m1 = mn1;
#pragma unroll
        for (int nf = 0; nf < 8; nf++) {
            o[nf][0] *= corr0; o[nf][1] *= corr0;
            o[nf][2] *= corr1; o[nf][3] *= corr1;
        }
        float rs0 = 0.f, rs1 = 0.f;
#pragma unroll
        for (int nf = 0; nf < 8; nf++) {
            sc[nf][0] = __expf(sc[nf][0] - m0);
            sc[nf][1] = __expf(sc[nf][1] - m0);
            sc[nf][2] = __expf(sc[nf][2] - m1);
            sc[nf][3] = __expf(sc[nf][3] - m1);
            rs0 += sc[nf][0] + sc[nf][1];
            rs1 += sc[nf][2] + sc[nf][3];
        }
        rs0 += __shfl_xor_sync(0xffffffffu, rs0, 1);
        rs0 += __shfl_xor_sync(0xffffffffu, rs0, 2);
        rs1 += __shfl_xor_sync(0xffffffffu, rs1, 1);
        rs1 += __shfl_xor_sync(0xffffffffu, rs1, 2);
        l0 = l0 * corr0 + rs0;
        l1 = l1 * corr1 + rs1;

        uint32_t ph[4][4], pl[4][4];
#pragma unroll
        for (int kk = 0; kk < 4; kk++) {
            float* s0 = sc[2 * kk];
            float* s1 = sc[2 * kk + 1];
            ph[kk][0] = pack_bf2(s0[0], s0[1]);
            ph[kk][1] = pack_bf2(s0[2], s0[3]);
            ph[kk][2] = pack_bf2(s1[0], s1[1]);
            ph[kk][3] = pack_bf2(s1[2], s1[3]);
            __nv_bfloat162 b;
            b = *(__nv_bfloat162*)&ph[kk][0];
            pl[kk][0] = pack_bf2(s0[0] - __bfloat162float(b.x), s0[1] - __bfloat162float(b.y));
            b = *(__nv_bfloat162*)&ph[kk][1];
            pl[kk][1] = pack_bf2(s0[2] - __bfloat162float(b.x), s0[3] - __bfloat162float(b.y));
            b = *(__nv_bfloat162*)&ph[kk][2];
            pl[kk][2] = pack_bf2(s1[0] - __bfloat162float(b.x), s1[1] - __bfloat162float(b.y));
            b = *(__nv_bfloat162*)&ph[kk][3];
            pl[kk][3] = pack_bf2(s1[2] - __bfloat162float(b.x), s1[3] - __bfloat162float(b.y));
        }

        int grp = lane >> 3;
#pragma unroll
        for (int kk = 0; kk < 4; kk++) {
#pragma unroll
            for (int j = 0; j < 4; j++) {
                int key = kk * 16 + (grp & 1) * 8 + (lane & 7);
                int dchunk = j * 2 + (grp >> 1);
                uint32_t soff = key * 128 + ((dchunk ^ (key & 7)) << 4);
                uint32_t r[4];
                LDSM_T4(r, Vh + soff);
                MMA_BF16(o[2 * j], ph[kk], r[0], r[1]);
                MMA_BF16(o[2 * j + 1], ph[kk], r[2], r[3]);
                MMA_BF16(o[2 * j], pl[kk], r[0], r[1]);
                MMA_BF16(o[2 * j + 1], pl[kk], r[2], r[3]);
                LDSM_T4(r, Vl + soff);
                MMA_BF16(o[2 * j], ph[kk], r[0], r[1]);
                MMA_BF16(o[2 * j + 1], ph[kk], r[2], r[3]);
            }
        }
    }
#undef ISSUE

    if (MODE == 0) {
        float inv0 = 1.f / l0, inv1 = 1.f / l1;
        int row0 = qrow0 - GL + g;
        int row1 = row0 + 8;
#pragma unroll
        for (int nf = 0; nf < 8; nf++) {
            int col = h * HD + nf * 8 + 2 * tq;
            uint32_t h0, lo0, h1, lo1;
            split2(o[nf][0] * inv0, o[nf][1] * inv0, h0, lo0);
            split2(o[nf][2] * inv1, o[nf][3] * inv1, h1, lo1);
            *(uint32_t*)(g_Xhi + (size_t)row0 * EMB + col) = h0;
            *(uint32_t*)(g_Xlo + (size_t)row0 * EMB + col) = lo0;
            *(uint32_t*)(g_Xhi + (size_t)row1 * EMB + col) = h1;
            *(uint32_t*)(g_Xlo + (size_t)row1 * EMB + col) = lo1;
        }
    } else {
        int qi0 = qrow0 + g;
        float* pp0 = g_part + (((size_t)h * GSPLIT + ks) * GL + qi0) * (HD + 2);
        float* pp1 = g_part + (((size_t)h * GSPLIT + ks) * GL + qi0 + 8) * (HD + 2);
        if (tq == 0) {
            pp0[0] = m0; pp0[1] = l0;
            pp1[0] = m1; pp1[1] = l1;
        }
#pragma unroll
        for (int nf = 0; nf < 8; nf++) {
            int col = nf * 8 + 2 * tq;
            pp0[2 + col] = o[nf][0]; pp0[2 + col + 1] = o[nf][1];
            pp1[2 + col] = o[nf][2]; pp1[2 + col + 1] = o[nf][3];
        }
    }
}

// ================= combine global-attn partials =================
__global__ __launch_bounds__(128) void gattn_combine() {
    int h = blockIdx.x;
    int qi = threadIdx.x;
    float M = -1e30f;
    for (int ks = 0; ks < GSPLIT; ks++) {
        const float* pp = g_part + (((size_t)h * GSPLIT + ks) * GL + qi) * (HD + 2);
        M = fmaxf(M, pp[0]);
    }
    float L = 0.f;
    float out[HD];
#pragma unroll
    for (int d = 0; d < HD; d++) out[d] = 0.f;
    for (int ks = 0; ks < GSPLIT; ks++) {
        const float* pp = g_part + (((size_t)h * GSPLIT + ks) * GL + qi) * (HD + 2);
        float w = __expf(pp[0] - M);
        L += pp[1] * w;
#pragma unroll
        for (int d = 0; d < HD; d++) out[d] += pp[2 + d] * w;
    }
    float inv = 1.f / L;
    size_t rbase = (size_t)(SEQ + qi) * EMB + h * HD;
#pragma unroll
    for (int d = 0; d < HD; d += 2) {
        uint32_t hw, lw;
        split2(out[d] * inv, out[d + 1] * inv, hw, lw);
        *(uint32_t*)(g_Xhi + rbase + d) = hw;
        *(uint32_t*)(g_Xlo + rbase + d) = lw;
    }
}

// ================= host =================
extern "C" void kernel_launch(void* const* d_in, const int* in_sizes, int n_in,
                              void* d_out, int out_size) {
    const float* tok = (const float*)d_in[0];
    const float* glob = (const float*)d_in[1];
    const float* mask = (const float*)d_in[2];
    const float* Wq = (const float*)d_in[3];
    const float* Wk = (const float*)d_in[4];
    const float* Wv = (const float*)d_in[5];
    const float* Wo = (const float*)d_in[6];
    float* out = (float*)d_out;

    static bool attr_done = false;
    if (!attr_done) {
        cudaFuncSetAttribute(gemm_qkv, cudaFuncAttributeMaxDynamicSharedMemorySize, 65536);
        cudaFuncSetAttribute(gemm_wo, cudaFuncAttributeMaxDynamicSharedMemorySize, 65536);
        cudaFuncSetAttribute(fmha<0>, cudaFuncAttributeMaxDynamicSharedMemorySize, 3 * STG);
        cudaFuncSetAttribute(fmha<1>, cudaFuncAttributeMaxDynamicSharedMemorySize, 3 * STG);
        attr_done = true;
    }

    // 1. convert inputs
    {
        size_t tot4 = (size_t)LTOT * EMB / 4;
        cvt_x<<<(unsigned)((tot4 + 255) / 256), 256>>>((const float4*)glob, (const float4*)tok);
    }
    cvt_w<<<dim3(32, 32, 4), dim3(32, 8)>>>(Wq, Wk, Wv, Wo);

    // 2. merged Q/K/V projections
    gemm_qkv<<<dim3(24, LTOT / 128), 256, 65536>>>();

    // 3. attention
    fmha<1><<<dim3(2, GSPLIT, NH), 128, 3 * STG>>>(mask);
    gattn_combine<<<NH, 128>>>();
    fmha<0><<<dim3(8, NB, NH), 128, 3 * STG>>>(mask);

    // 4. output projection -> d_out
    gemm_wo<<<dim3(8, LTOT / 128), 256, 65536>>>(out);
}